// round 7
// baseline (speedup 1.0000x reference)
#include <cuda_runtime.h>
#include <math.h>

// Problem constants
#define B_IMG   32
#define HW      56
#define CCH     192
#define NHEAD   6
#define HDIM    32
#define NTOK    49
#define NWIN    64
#define BWIN    2048
#define TOK     100352
#define SHIFT_  3
#define QSCALE  0.17677669529663687f

// swizzled tile sizes (floats)
#define QT_SZ   2112    // 16 blocks * 132
#define KT_SZ   1904    // 28 blocks * 68
#define BM_SZ   3840    // 64 rows * 60

// ---------------- scratch ----------------
__device__ float g_xw [ (size_t)TOK * CCH ];
__device__ float g_q  [ (size_t)BWIN * NHEAD * QT_SZ ];   // swizzled tf32
__device__ float g_k  [ (size_t)BWIN * NHEAD * KT_SZ ];   // swizzled tf32
__device__ float g_v  [ (size_t)BWIN * NHEAD * KT_SZ ];   // swizzled tf32 (transposed)
__device__ float g_ctx[ (size_t)TOK * CCH ];
__device__ float g_y  [ (size_t)TOK * CCH ];
__device__ float g_bm [ (size_t)NHEAD * NWIN * BM_SZ ];   // bias+mask, padded -1e9

// ---------------- K0: combined bias+mask table ----------------
__global__ void bias2_kernel(const float* __restrict__ table, const int* __restrict__ idx,
                             const float* __restrict__ mask)
{
    int i = blockIdx.x * blockDim.x + threadIdx.x;
    if (i >= NHEAD * NWIN * BM_SZ) return;
    int c  = i % 60;
    int r  = (i / 60) & 63;
    int wi = (i / BM_SZ) & 63;
    int h  = i / (BM_SZ * NWIN);
    float v = -1e9f;
    if (r < NTOK && c < NTOK)
        v = table[idx[r * NTOK + c] * NHEAD + h] + mask[(wi * NTOK + r) * NTOK + c];
    g_bm[i] = v;
}

// ---------------- K0b: zero K/V pad rows (blocks 24..27 of each tile) -------
__global__ void zero_pads_kernel()
{
    int i = blockIdx.x * blockDim.x + threadIdx.x;
    if (i >= BWIN * NHEAD * 272) return;
    int tile = i / 272, j = i % 272;
    size_t off = (size_t)tile * KT_SZ + 1632 + j;
    g_k[off] = 0.f;
    g_v[off] = 0.f;
}

// ---------------- K1: LN + shift + window partition ----------------
__global__ void __launch_bounds__(256) ln_kernel(const float* __restrict__ x,
                                                 const float* __restrict__ g,
                                                 const float* __restrict__ b)
{
    int wid  = (blockIdx.x * blockDim.x + threadIdx.x) >> 5;
    int lane = threadIdx.x & 31;
    if (wid >= TOK) return;

    int w  = wid / NTOK, n = wid % NTOK;
    int bb = w >> 6, wi = w & 63;
    int wh = wi >> 3, ww = wi & 7;
    int ii = n / 7,  jj = n % 7;
    int hh = (wh * 7 + ii + SHIFT_) % HW;
    int w2 = (ww * 7 + jj + SHIFT_) % HW;
    const float* src = x + ((size_t)bb * (HW * HW) + hh * HW + w2) * CCH;

    float vals[6];
    float s = 0.f, s2 = 0.f;
#pragma unroll
    for (int u = 0; u < 6; u++) {
        float v = src[lane + u * 32];
        vals[u] = v; s += v; s2 += v * v;
    }
#pragma unroll
    for (int off = 16; off; off >>= 1) {
        s  += __shfl_xor_sync(0xFFFFFFFFu, s,  off);
        s2 += __shfl_xor_sync(0xFFFFFFFFu, s2, off);
    }
    float mu  = s * (1.f / CCH);
    float var = s2 * (1.f / CCH) - mu * mu;
    float inv = rsqrtf(var + 1e-5f);

    float* dst = g_xw + (size_t)wid * CCH;
#pragma unroll
    for (int u = 0; u < 6; u++) {
        int c = lane + u * 32;
        dst[c] = (vals[u] - mu) * inv * g[c] + b[c];
    }
}

// ---------------- tf32 helpers ----------------
__device__ __forceinline__ float to_tf32(float x) {
    unsigned u;
    asm("cvt.rna.tf32.f32 %0, %1;" : "=r"(u) : "f"(x));
    return __uint_as_float(u);
}
__device__ __forceinline__ unsigned tf32u(float x) {
    unsigned u;
    asm("cvt.rna.tf32.f32 %0, %1;" : "=r"(u) : "f"(x));
    return u;
}

__device__ __forceinline__ void mma_tf32(float* d, const unsigned* a, const unsigned* b) {
    asm volatile(
        "mma.sync.aligned.m16n8k8.row.col.f32.tf32.tf32.f32 "
        "{%0,%1,%2,%3}, {%4,%5,%6,%7}, {%8,%9}, {%0,%1,%2,%3};\n"
        : "+f"(d[0]), "+f"(d[1]), "+f"(d[2]), "+f"(d[3])
        : "r"(a[0]), "r"(a[1]), "r"(a[2]), "r"(a[3]), "r"(b[0]), "r"(b[1]));
}

// ---------------- tf32 MMA GEMM (double-buffered) ---------------------------
template<int EPI>
__global__ void __launch_bounds__(256) gemm_kernel(const float* __restrict__ W,
                                                   const float* __restrict__ bias,
                                                   const float* __restrict__ resid,
                                                   float* __restrict__ out)
{
    const float* A = (EPI == 0) ? g_xw : (EPI == 1 ? g_ctx : g_y);

    __shared__ __align__(16) float As[2][32 * 132];
    __shared__ __align__(16) float Bs[2][32 * 68];

    int tid  = threadIdx.x;
    int lane = tid & 31, wid = tid >> 5;
    int wm = wid >> 1, wn = wid & 1;
    int gid = lane >> 2, qid = lane & 3;
    int row0 = blockIdx.y * 128;
    int col0 = blockIdx.x * 64;

    float acc[2][4][4];
#pragma unroll
    for (int i = 0; i < 2; i++)
#pragma unroll
        for (int j = 0; j < 4; j++)
#pragma unroll
            for (int r = 0; r < 4; r++) acc[i][j][r] = 0.f;

    float4 a_ld[4], b_ld[2];
    int a_r[4], a_k[4], b_r[2], b_k[2];
#pragma unroll
    for (int i = 0; i < 4; i++) {
        int f = tid + i * 256;
        a_r[i] = f >> 3; a_k[i] = (f & 7) << 2;
    }
#pragma unroll
    for (int i = 0; i < 2; i++) {
        int f = tid + i * 256;
        b_r[i] = f >> 3; b_k[i] = (f & 7) << 2;
    }

#pragma unroll
    for (int i = 0; i < 4; i++)
        a_ld[i] = *(const float4*)(A + (size_t)(row0 + a_r[i]) * CCH + a_k[i]);
#pragma unroll
    for (int i = 0; i < 2; i++)
        b_ld[i] = *(const float4*)(W + (size_t)(col0 + b_r[i]) * CCH + b_k[i]);

    // store stage 0
#pragma unroll
    for (int i = 0; i < 4; i++) {
        int r = a_r[i], kk = a_k[i];
        int off = ((r >> 4) * 4 + (kk >> 3)) * 132 + (r & 7) * 16
                + ((r >> 3) & 1) + (((kk >> 2) & 1) << 1);
        As[0][off +  0] = to_tf32(a_ld[i].x);
        As[0][off +  4] = to_tf32(a_ld[i].y);
        As[0][off +  8] = to_tf32(a_ld[i].z);
        As[0][off + 12] = to_tf32(a_ld[i].w);
    }
#pragma unroll
    for (int i = 0; i < 2; i++) {
        int r = b_r[i], kk = b_k[i];
        int off = ((r >> 3) * 4 + (kk >> 3)) * 68 + (r & 7) * 8 + ((kk >> 2) & 1);
        Bs[0][off + 0] = to_tf32(b_ld[i].x);
        Bs[0][off + 2] = to_tf32(b_ld[i].y);
        Bs[0][off + 4] = to_tf32(b_ld[i].z);
        Bs[0][off + 6] = to_tf32(b_ld[i].w);
    }
    __syncthreads();

#pragma unroll
    for (int it = 0; it < 6; it++) {
        int cur = it & 1, nxt = cur ^ 1;
        if (it < 5) {
            int k0 = (it + 1) * 32;
#pragma unroll
            for (int i = 0; i < 4; i++)
                a_ld[i] = *(const float4*)(A + (size_t)(row0 + a_r[i]) * CCH + k0 + a_k[i]);
#pragma unroll
            for (int i = 0; i < 2; i++)
                b_ld[i] = *(const float4*)(W + (size_t)(col0 + b_r[i]) * CCH + k0 + b_k[i]);
        }

#pragma unroll
        for (int ks8 = 0; ks8 < 4; ks8++) {
            float4 af0 = *(const float4*)&As[cur][((wm * 2 + 0) * 4 + ks8) * 132 + lane * 4];
            float4 af1 = *(const float4*)&As[cur][((wm * 2 + 1) * 4 + ks8) * 132 + lane * 4];
            float2 bf[4];
#pragma unroll
            for (int ni = 0; ni < 4; ni++)
                bf[ni] = *(const float2*)&Bs[cur][((wn * 4 + ni) * 4 + ks8) * 68 + lane * 2];
#pragma unroll
            for (int ni = 0; ni < 4; ni++) {
                mma_tf32(acc[0][ni], (const unsigned*)&af0, (const unsigned*)&bf[ni]);
                mma_tf32(acc[1][ni], (const unsigned*)&af1, (const unsigned*)&bf[ni]);
            }
        }

        if (it < 5) {
#pragma unroll
            for (int i = 0; i < 4; i++) {
                int r = a_r[i], kk = a_k[i];
                int off = ((r >> 4) * 4 + (kk >> 3)) * 132 + (r & 7) * 16
                        + ((r >> 3) & 1) + (((kk >> 2) & 1) << 1);
                As[nxt][off +  0] = to_tf32(a_ld[i].x);
                As[nxt][off +  4] = to_tf32(a_ld[i].y);
                As[nxt][off +  8] = to_tf32(a_ld[i].z);
                As[nxt][off + 12] = to_tf32(a_ld[i].w);
            }
#pragma unroll
            for (int i = 0; i < 2; i++) {
                int r = b_r[i], kk = b_k[i];
                int off = ((r >> 3) * 4 + (kk >> 3)) * 68 + (r & 7) * 8 + ((kk >> 2) & 1);
                Bs[nxt][off + 0] = to_tf32(b_ld[i].x);
                Bs[nxt][off + 2] = to_tf32(b_ld[i].y);
                Bs[nxt][off + 4] = to_tf32(b_ld[i].z);
                Bs[nxt][off + 6] = to_tf32(b_ld[i].w);
            }
            __syncthreads();
        }
    }

#pragma unroll
    for (int mi = 0; mi < 2; mi++) {
#pragma unroll
        for (int reg = 0; reg < 4; reg++) {
            int r = row0 + wm * 32 + mi * 16 + gid + ((reg >= 2) ? 8 : 0);
            int w = r / NTOK, n = r % NTOK;
            if (EPI == 0) {
#pragma unroll
                for (int ni = 0; ni < 4; ni++) {
                    int o = col0 + wn * 32 + ni * 8 + qid * 2 + (reg & 1);
                    float val = acc[mi][ni][reg] + bias[o];
                    int m = o / CCH, rem = o % CCH;
                    int h = rem >> 5, d = rem & 31;
                    size_t tb = (size_t)(w * NHEAD + h);
                    if (m == 0) {
                        int off = ((n >> 4) * 4 + (d >> 3)) * 132 + (n & 7) * 16
                                + ((n >> 3) & 1) + (((d >> 2) & 1) << 1) + (d & 3) * 4;
                        g_q[tb * QT_SZ + off] = to_tf32(val * QSCALE);
                    } else if (m == 1) {
                        int off = ((n >> 3) * 4 + (d >> 3)) * 68 + (n & 7) * 8
                                + ((d >> 2) & 1) + (d & 3) * 2;
                        g_k[tb * KT_SZ + off] = to_tf32(val);
                    } else {
                        int off = ((n >> 3) * 4 + (d >> 3)) * 68 + (d & 7) * 8
                                + (n & 3) * 2 + ((n >> 2) & 1);
                        g_v[tb * KT_SZ + off] = to_tf32(val);
                    }
                }
            } else if (EPI == 1) {
                int bb = w >> 6, wi = w & 63;
                int wh = wi >> 3, ww = wi & 7;
                int ii = n / 7, jj = n % 7;
                int hh = (wh * 7 + ii + SHIFT_) % HW;
                int w2 = (ww * 7 + jj + SHIFT_) % HW;
                float* dst = g_y + ((size_t)bb * (HW * HW) + hh * HW + w2) * CCH;
#pragma unroll
                for (int ni = 0; ni < 4; ni++) {
                    int c = col0 + wn * 32 + ni * 8 + qid * 2 + (reg & 1);
                    dst[c] = acc[mi][ni][reg] + bias[c];
                }
            } else {
                const float* rs = resid + (size_t)r * CCH;
                float* dp = out + (size_t)r * CCH;
#pragma unroll
                for (int ni = 0; ni < 4; ni++) {
                    int c = col0 + wn * 32 + ni * 8 + qid * 2 + (reg & 1);
                    float v = acc[mi][ni][reg] + bias[c];
                    float ge = 0.5f * v * (1.f + erff(v * 0.70710678118654752f));
                    dp[c] = rs[c] + ge;
                }
            }
        }
    }
}

// ---------------- K3: windowed attention — no smem, direct fragment loads ---
__global__ void __launch_bounds__(128) attn_kernel()
{
    int w = blockIdx.x, h = blockIdx.y;
    int tid = threadIdx.x;
    int lane = tid & 31, wrp = tid >> 5;
    int gid = lane >> 2, qid = lane & 3;

    size_t tb = (size_t)(w * NHEAD + h);
    const float* __restrict__ qt = g_q + tb * QT_SZ;
    const float* __restrict__ kt = g_k + tb * KT_SZ;
    const float* __restrict__ vt = g_v + tb * KT_SZ;
    const float* __restrict__ bmp = g_bm + ((size_t)h * NWIN + (w & 63)) * BM_SZ;

    int m0 = wrp * 16;

    // ---- S = Q K^T : fragments straight from global ----
    float sacc[7][4];
#pragma unroll
    for (int nt = 0; nt < 7; nt++)
#pragma unroll
        for (int r = 0; r < 4; r++) sacc[nt][r] = 0.f;

#pragma unroll
    for (int k8 = 0; k8 < 4; k8++) {
        float4 av = *(const float4*)&qt[(wrp * 4 + k8) * 132 + lane * 4];
#pragma unroll
        for (int nt = 0; nt < 7; nt++) {
            float2 bv = *(const float2*)&kt[(nt * 4 + k8) * 68 + lane * 2];
            mma_tf32(sacc[nt], (const unsigned*)&av, (const unsigned*)&bv);
        }
    }

    // ---- + bias + mask (from L2-resident precomputed table) ----
#pragma unroll
    for (int nt = 0; nt < 7; nt++) {
        float2 t0 = *(const float2*)&bmp[(m0 + gid) * 60 + nt * 8 + 2 * qid];
        float2 t1 = *(const float2*)&bmp[(m0 + gid + 8) * 60 + nt * 8 + 2 * qid];
        sacc[nt][0] += t0.x; sacc[nt][1] += t0.y;
        sacc[nt][2] += t1.x; sacc[nt][3] += t1.y;
    }

    // ---- softmax in registers ----
    float mx0 = -1e30f, mx1 = -1e30f;
#pragma unroll
    for (int nt = 0; nt < 7; nt++) {
        mx0 = fmaxf(mx0, fmaxf(sacc[nt][0], sacc[nt][1]));
        mx1 = fmaxf(mx1, fmaxf(sacc[nt][2], sacc[nt][3]));
    }
    mx0 = fmaxf(mx0, __shfl_xor_sync(0xFFFFFFFFu, mx0, 1));
    mx0 = fmaxf(mx0, __shfl_xor_sync(0xFFFFFFFFu, mx0, 2));
    mx1 = fmaxf(mx1, __shfl_xor_sync(0xFFFFFFFFu, mx1, 1));
    mx1 = fmaxf(mx1, __shfl_xor_sync(0xFFFFFFFFu, mx1, 2));

    float sum0 = 0.f, sum1 = 0.f;
#pragma unroll
    for (int nt = 0; nt < 7; nt++) {
        sacc[nt][0] = __expf(sacc[nt][0] - mx0);
        sacc[nt][1] = __expf(sacc[nt][1] - mx0);
        sacc[nt][2] = __expf(sacc[nt][2] - mx1);
        sacc[nt][3] = __expf(sacc[nt][3] - mx1);
        sum0 += sacc[nt][0] + sacc[nt][1];
        sum1 += sacc[nt][2] + sacc[nt][3];
    }
    sum0 += __shfl_xor_sync(0xFFFFFFFFu, sum0, 1);
    sum0 += __shfl_xor_sync(0xFFFFFFFFu, sum0, 2);
    sum1 += __shfl_xor_sync(0xFFFFFFFFu, sum1, 1);
    sum1 += __shfl_xor_sync(0xFFFFFFFFu, sum1, 2);
    float inv0 = 1.f / sum0, inv1 = 1.f / sum1;
#pragma unroll
    for (int nt = 0; nt < 7; nt++) {
        sacc[nt][0] *= inv0; sacc[nt][1] *= inv0;
        sacc[nt][2] *= inv1; sacc[nt][3] *= inv1;
    }

    // ---- O = P V : re-fragment P via shuffles, V fragments from global ----
    float o[4][4];
#pragma unroll
    for (int nt = 0; nt < 4; nt++)
#pragma unroll
        for (int r = 0; r < 4; r++) o[nt][r] = 0.f;

    int src0 = (lane & ~3) | (qid >> 1);
    int src1 = src0 + 2;
    bool odd = (qid & 1);

#pragma unroll
    for (int kt2 = 0; kt2 < 7; kt2++) {
        float p00 = __shfl_sync(0xFFFFFFFFu, sacc[kt2][0], src0);
        float p01 = __shfl_sync(0xFFFFFFFFu, sacc[kt2][1], src0);
        float p10 = __shfl_sync(0xFFFFFFFFu, sacc[kt2][0], src1);
        float p11 = __shfl_sync(0xFFFFFFFFu, sacc[kt2][1], src1);
        float p20 = __shfl_sync(0xFFFFFFFFu, sacc[kt2][2], src0);
        float p21 = __shfl_sync(0xFFFFFFFFu, sacc[kt2][3], src0);
        float p30 = __shfl_sync(0xFFFFFFFFu, sacc[kt2][2], src1);
        float p31 = __shfl_sync(0xFFFFFFFFu, sacc[kt2][3], src1);
        unsigned a[4];
        a[0] = tf32u(odd ? p01 : p00);
        a[1] = tf32u(odd ? p21 : p20);
        a[2] = tf32u(odd ? p11 : p10);
        a[3] = tf32u(odd ? p31 : p30);
#pragma unroll
        for (int nt = 0; nt < 4; nt++) {
            float2 bv = *(const float2*)&vt[(kt2 * 4 + nt) * 68 + lane * 2];
            mma_tf32(o[nt], a, (const unsigned*)&bv);
        }
    }

    // ---- write ctx ----
    int r0 = m0 + gid, r1 = r0 + 8;
    float* op = g_ctx + ((size_t)w * NTOK) * CCH + h * HDIM;
#pragma unroll
    for (int nt = 0; nt < 4; nt++) {
        int d = nt * 8 + 2 * qid;
        if (r0 < NTOK) { float2 t = make_float2(o[nt][0], o[nt][1]); *(float2*)&op[r0 * CCH + d] = t; }
        if (r1 < NTOK) { float2 t = make_float2(o[nt][2], o[nt][3]); *(float2*)&op[r1 * CCH + d] = t; }
    }
}

// ---------------- launch ----------------
extern "C" void kernel_launch(void* const* d_in, const int* in_sizes, int n_in,
                              void* d_out, int out_size)
{
    const float* inputs = (const float*)d_in[0];
    const float* amask  = (const float*)d_in[1];
    const float* n1g    = (const float*)d_in[2];
    const float* n1b    = (const float*)d_in[3];
    const float* qkvw   = (const float*)d_in[4];
    const float* qkvb   = (const float*)d_in[5];
    const float* rpt    = (const float*)d_in[6];
    const int*   rpi    = (const int*)d_in[7];
    const float* pw     = (const float*)d_in[8];
    const float* pb     = (const float*)d_in[9];
    const float* lw     = (const float*)d_in[10];
    const float* lb     = (const float*)d_in[11];
    float* out = (float*)d_out;

    bias2_kernel<<<(NHEAD * NWIN * BM_SZ + 255) / 256, 256>>>(rpt, rpi, amask);
    zero_pads_kernel<<<(BWIN * NHEAD * 272 + 255) / 256, 256>>>();
    ln_kernel<<<TOK / 8, 256>>>(inputs, n1g, n1b);
    gemm_kernel<0><<<dim3(9, TOK / 128), 256>>>(qkvw, qkvb, nullptr, nullptr);
    attn_kernel<<<dim3(BWIN, NHEAD), 128>>>();
    gemm_kernel<1><<<dim3(3, TOK / 128), 256>>>(pw, pb, nullptr, nullptr);
    gemm_kernel<2><<<dim3(3, TOK / 128), 256>>>(lw, lb, inputs, out);
}

// round 8
// speedup vs baseline: 1.1541x; 1.1541x over previous
#include <cuda_runtime.h>
#include <math.h>

// Problem constants
#define B_IMG   32
#define HW      56
#define CCH     192
#define NHEAD   6
#define HDIM    32
#define NTOK    49
#define NWIN    64
#define BWIN    2048
#define TOK     100352
#define SHIFT_  3
#define QSCALE  0.17677669529663687f

// swizzled tile sizes (floats)
#define QT_SZ   2112    // 16 blocks * 132
#define KT_SZ   1904    // 28 blocks * 68
#define BM_SZ   3840    // 64 rows * 60

// ---------------- scratch ----------------
__device__ float g_xw [ (size_t)TOK * CCH ];
__device__ float g_q  [ (size_t)BWIN * NHEAD * QT_SZ ];   // swizzled (tf32-compatible f32)
__device__ float g_k  [ (size_t)BWIN * NHEAD * KT_SZ ];
__device__ float g_v  [ (size_t)BWIN * NHEAD * KT_SZ ];   // transposed
__device__ float g_ctx[ (size_t)TOK * CCH ];
__device__ float g_y  [ (size_t)TOK * CCH ];
__device__ float g_bm [ (size_t)NHEAD * NWIN * BM_SZ ];   // bias+mask, padded -1e9

// ---------------- K0: combined bias+mask table ----------------
__global__ void bias2_kernel(const float* __restrict__ table, const int* __restrict__ idx,
                             const float* __restrict__ mask)
{
    int i = blockIdx.x * blockDim.x + threadIdx.x;
    if (i >= NHEAD * NWIN * BM_SZ) return;
    int c  = i % 60;
    int r  = (i / 60) & 63;
    int wi = (i / BM_SZ) & 63;
    int h  = i / (BM_SZ * NWIN);
    float v = -1e9f;
    if (r < NTOK && c < NTOK)
        v = table[idx[r * NTOK + c] * NHEAD + h] + mask[(wi * NTOK + r) * NTOK + c];
    g_bm[i] = v;
}

// ---------------- K0b: zero K/V pad rows (blocks 24..27 of each tile) -------
__global__ void zero_pads_kernel()
{
    int i = blockIdx.x * blockDim.x + threadIdx.x;
    if (i >= BWIN * NHEAD * 272) return;
    int tile = i / 272, j = i % 272;
    size_t off = (size_t)tile * KT_SZ + 1632 + j;
    g_k[off] = 0.f;
    g_v[off] = 0.f;
}

// ---------------- K1: LN + shift + window partition ----------------
__global__ void __launch_bounds__(256) ln_kernel(const float* __restrict__ x,
                                                 const float* __restrict__ g,
                                                 const float* __restrict__ b)
{
    int wid  = (blockIdx.x * blockDim.x + threadIdx.x) >> 5;
    int lane = threadIdx.x & 31;
    if (wid >= TOK) return;

    int w  = wid / NTOK, n = wid % NTOK;
    int bb = w >> 6, wi = w & 63;
    int wh = wi >> 3, ww = wi & 7;
    int ii = n / 7,  jj = n % 7;
    int hh = (wh * 7 + ii + SHIFT_) % HW;
    int w2 = (ww * 7 + jj + SHIFT_) % HW;
    const float* src = x + ((size_t)bb * (HW * HW) + hh * HW + w2) * CCH;

    float vals[6];
    float s = 0.f, s2 = 0.f;
#pragma unroll
    for (int u = 0; u < 6; u++) {
        float v = src[lane + u * 32];
        vals[u] = v; s += v; s2 += v * v;
    }
#pragma unroll
    for (int off = 16; off; off >>= 1) {
        s  += __shfl_xor_sync(0xFFFFFFFFu, s,  off);
        s2 += __shfl_xor_sync(0xFFFFFFFFu, s2, off);
    }
    float mu  = s * (1.f / CCH);
    float var = s2 * (1.f / CCH) - mu * mu;
    float inv = rsqrtf(var + 1e-5f);

    float* dst = g_xw + (size_t)wid * CCH;
#pragma unroll
    for (int u = 0; u < 6; u++) {
        int c = lane + u * 32;
        dst[c] = (vals[u] - mu) * inv * g[c] + b[c];
    }
}

__device__ __forceinline__ void mma_tf32(float* d, const unsigned* a, const unsigned* b) {
    asm volatile(
        "mma.sync.aligned.m16n8k8.row.col.f32.tf32.tf32.f32 "
        "{%0,%1,%2,%3}, {%4,%5,%6,%7}, {%8,%9}, {%0,%1,%2,%3};\n"
        : "+f"(d[0]), "+f"(d[1]), "+f"(d[2]), "+f"(d[3])
        : "r"(a[0]), "r"(a[1]), "r"(a[2]), "r"(a[3]), "r"(b[0]), "r"(b[1]));
}

// ---------------- tf32 MMA GEMM (double-buffered, 3 CTAs/SM) ----------------
template<int EPI>
__global__ void __launch_bounds__(256, 3) gemm_kernel(const float* __restrict__ W,
                                                      const float* __restrict__ bias,
                                                      const float* __restrict__ resid,
                                                      float* __restrict__ out)
{
    const float* A = (EPI == 0) ? g_xw : (EPI == 1 ? g_ctx : g_y);

    __shared__ __align__(16) float As[2][32 * 132];
    __shared__ __align__(16) float Bs[2][32 * 68];

    int tid  = threadIdx.x;
    int lane = tid & 31, wid = tid >> 5;
    int wm = wid >> 1, wn = wid & 1;
    int gid = lane >> 2, qid = lane & 3;
    int row0 = blockIdx.y * 128;
    int col0 = blockIdx.x * 64;

    float acc[2][4][4];
#pragma unroll
    for (int i = 0; i < 2; i++)
#pragma unroll
        for (int j = 0; j < 4; j++)
#pragma unroll
            for (int r = 0; r < 4; r++) acc[i][j][r] = 0.f;

    float4 a_ld[4], b_ld[2];
    int a_r[4], a_k[4], b_r[2], b_k[2];
#pragma unroll
    for (int i = 0; i < 4; i++) {
        int f = tid + i * 256;
        a_r[i] = f >> 3; a_k[i] = (f & 7) << 2;
    }
#pragma unroll
    for (int i = 0; i < 2; i++) {
        int f = tid + i * 256;
        b_r[i] = f >> 3; b_k[i] = (f & 7) << 2;
    }

#pragma unroll
    for (int i = 0; i < 4; i++)
        a_ld[i] = *(const float4*)(A + (size_t)(row0 + a_r[i]) * CCH + a_k[i]);
#pragma unroll
    for (int i = 0; i < 2; i++)
        b_ld[i] = *(const float4*)(W + (size_t)(col0 + b_r[i]) * CCH + b_k[i]);

    // store stage 0 (raw f32; mma.tf32 truncates mantissa — within tolerance)
#pragma unroll
    for (int i = 0; i < 4; i++) {
        int r = a_r[i], kk = a_k[i];
        int off = ((r >> 4) * 4 + (kk >> 3)) * 132 + (r & 7) * 16
                + ((r >> 3) & 1) + (((kk >> 2) & 1) << 1);
        As[0][off +  0] = a_ld[i].x;
        As[0][off +  4] = a_ld[i].y;
        As[0][off +  8] = a_ld[i].z;
        As[0][off + 12] = a_ld[i].w;
    }
#pragma unroll
    for (int i = 0; i < 2; i++) {
        int r = b_r[i], kk = b_k[i];
        int off = ((r >> 3) * 4 + (kk >> 3)) * 68 + (r & 7) * 8 + ((kk >> 2) & 1);
        Bs[0][off + 0] = b_ld[i].x;
        Bs[0][off + 2] = b_ld[i].y;
        Bs[0][off + 4] = b_ld[i].z;
        Bs[0][off + 6] = b_ld[i].w;
    }
    __syncthreads();

#pragma unroll
    for (int it = 0; it < 6; it++) {
        int cur = it & 1, nxt = cur ^ 1;
        if (it < 5) {
            int k0 = (it + 1) * 32;
#pragma unroll
            for (int i = 0; i < 4; i++)
                a_ld[i] = *(const float4*)(A + (size_t)(row0 + a_r[i]) * CCH + k0 + a_k[i]);
#pragma unroll
            for (int i = 0; i < 2; i++)
                b_ld[i] = *(const float4*)(W + (size_t)(col0 + b_r[i]) * CCH + k0 + b_k[i]);
        }

#pragma unroll
        for (int ks8 = 0; ks8 < 4; ks8++) {
            float4 af0 = *(const float4*)&As[cur][((wm * 2 + 0) * 4 + ks8) * 132 + lane * 4];
            float4 af1 = *(const float4*)&As[cur][((wm * 2 + 1) * 4 + ks8) * 132 + lane * 4];
            float2 bf[4];
#pragma unroll
            for (int ni = 0; ni < 4; ni++)
                bf[ni] = *(const float2*)&Bs[cur][((wn * 4 + ni) * 4 + ks8) * 68 + lane * 2];
#pragma unroll
            for (int ni = 0; ni < 4; ni++) {
                mma_tf32(acc[0][ni], (const unsigned*)&af0, (const unsigned*)&bf[ni]);
                mma_tf32(acc[1][ni], (const unsigned*)&af1, (const unsigned*)&bf[ni]);
            }
        }

        if (it < 5) {
#pragma unroll
            for (int i = 0; i < 4; i++) {
                int r = a_r[i], kk = a_k[i];
                int off = ((r >> 4) * 4 + (kk >> 3)) * 132 + (r & 7) * 16
                        + ((r >> 3) & 1) + (((kk >> 2) & 1) << 1);
                As[nxt][off +  0] = a_ld[i].x;
                As[nxt][off +  4] = a_ld[i].y;
                As[nxt][off +  8] = a_ld[i].z;
                As[nxt][off + 12] = a_ld[i].w;
            }
#pragma unroll
            for (int i = 0; i < 2; i++) {
                int r = b_r[i], kk = b_k[i];
                int off = ((r >> 3) * 4 + (kk >> 3)) * 68 + (r & 7) * 8 + ((kk >> 2) & 1);
                Bs[nxt][off + 0] = b_ld[i].x;
                Bs[nxt][off + 2] = b_ld[i].y;
                Bs[nxt][off + 4] = b_ld[i].z;
                Bs[nxt][off + 6] = b_ld[i].w;
            }
            __syncthreads();
        }
    }

#pragma unroll
    for (int mi = 0; mi < 2; mi++) {
#pragma unroll
        for (int reg = 0; reg < 4; reg++) {
            int r = row0 + wm * 32 + mi * 16 + gid + ((reg >= 2) ? 8 : 0);
            int w = r / NTOK, n = r % NTOK;
            if (EPI == 0) {
#pragma unroll
                for (int ni = 0; ni < 4; ni++) {
                    int o = col0 + wn * 32 + ni * 8 + qid * 2 + (reg & 1);
                    float val = acc[mi][ni][reg] + bias[o];
                    int m = o / CCH, rem = o % CCH;
                    int h = rem >> 5, d = rem & 31;
                    size_t tb = (size_t)(w * NHEAD + h);
                    if (m == 0) {
                        int off = ((n >> 4) * 4 + (d >> 3)) * 132 + (n & 7) * 16
                                + ((n >> 3) & 1) + (((d >> 2) & 1) << 1) + (d & 3) * 4;
                        g_q[tb * QT_SZ + off] = val * QSCALE;
                    } else if (m == 1) {
                        int off = ((n >> 3) * 4 + (d >> 3)) * 68 + (n & 7) * 8
                                + ((d >> 2) & 1) + (d & 3) * 2;
                        g_k[tb * KT_SZ + off] = val;
                    } else {
                        int off = ((n >> 3) * 4 + (d >> 3)) * 68 + (d & 7) * 8
                                + (n & 3) * 2 + ((n >> 2) & 1);
                        g_v[tb * KT_SZ + off] = val;
                    }
                }
            } else if (EPI == 1) {
                int bb = w >> 6, wi = w & 63;
                int wh = wi >> 3, ww = wi & 7;
                int ii = n / 7, jj = n % 7;
                int hh = (wh * 7 + ii + SHIFT_) % HW;
                int w2 = (ww * 7 + jj + SHIFT_) % HW;
                float* dst = g_y + ((size_t)bb * (HW * HW) + hh * HW + w2) * CCH;
#pragma unroll
                for (int ni = 0; ni < 4; ni++) {
                    int c = col0 + wn * 32 + ni * 8 + qid * 2 + (reg & 1);
                    dst[c] = acc[mi][ni][reg] + bias[c];
                }
            } else {
                const float* rs = resid + (size_t)r * CCH;
                float* dp = out + (size_t)r * CCH;
#pragma unroll
                for (int ni = 0; ni < 4; ni++) {
                    int c = col0 + wn * 32 + ni * 8 + qid * 2 + (reg & 1);
                    float v = acc[mi][ni][reg] + bias[c];
                    float ge = 0.5f * v * (1.f + erff(v * 0.70710678118654752f));
                    dp[c] = rs[c] + ge;
                }
            }
        }
    }
}

// ---------------- K3: windowed attention — no smem, direct fragment loads ---
__global__ void __launch_bounds__(128) attn_kernel()
{
    int w = blockIdx.x, h = blockIdx.y;
    int tid = threadIdx.x;
    int lane = tid & 31, wrp = tid >> 5;
    int gid = lane >> 2, qid = lane & 3;

    size_t tb = (size_t)(w * NHEAD + h);
    const float* __restrict__ qt = g_q + tb * QT_SZ;
    const float* __restrict__ kt = g_k + tb * KT_SZ;
    const float* __restrict__ vt = g_v + tb * KT_SZ;
    const float* __restrict__ bmp = g_bm + ((size_t)h * NWIN + (w & 63)) * BM_SZ;

    int m0 = wrp * 16;

    // ---- S = Q K^T ----
    float sacc[7][4];
#pragma unroll
    for (int nt = 0; nt < 7; nt++)
#pragma unroll
        for (int r = 0; r < 4; r++) sacc[nt][r] = 0.f;

#pragma unroll
    for (int k8 = 0; k8 < 4; k8++) {
        float4 av = *(const float4*)&qt[(wrp * 4 + k8) * 132 + lane * 4];
#pragma unroll
        for (int nt = 0; nt < 7; nt++) {
            float2 bv = *(const float2*)&kt[(nt * 4 + k8) * 68 + lane * 2];
            mma_tf32(sacc[nt], (const unsigned*)&av, (const unsigned*)&bv);
        }
    }

    // ---- + bias + mask ----
#pragma unroll
    for (int nt = 0; nt < 7; nt++) {
        float2 t0 = *(const float2*)&bmp[(m0 + gid) * 60 + nt * 8 + 2 * qid];
        float2 t1 = *(const float2*)&bmp[(m0 + gid + 8) * 60 + nt * 8 + 2 * qid];
        sacc[nt][0] += t0.x; sacc[nt][1] += t0.y;
        sacc[nt][2] += t1.x; sacc[nt][3] += t1.y;
    }

    // ---- softmax in registers ----
    float mx0 = -1e30f, mx1 = -1e30f;
#pragma unroll
    for (int nt = 0; nt < 7; nt++) {
        mx0 = fmaxf(mx0, fmaxf(sacc[nt][0], sacc[nt][1]));
        mx1 = fmaxf(mx1, fmaxf(sacc[nt][2], sacc[nt][3]));
    }
    mx0 = fmaxf(mx0, __shfl_xor_sync(0xFFFFFFFFu, mx0, 1));
    mx0 = fmaxf(mx0, __shfl_xor_sync(0xFFFFFFFFu, mx0, 2));
    mx1 = fmaxf(mx1, __shfl_xor_sync(0xFFFFFFFFu, mx1, 1));
    mx1 = fmaxf(mx1, __shfl_xor_sync(0xFFFFFFFFu, mx1, 2));

    float sum0 = 0.f, sum1 = 0.f;
#pragma unroll
    for (int nt = 0; nt < 7; nt++) {
        sacc[nt][0] = __expf(sacc[nt][0] - mx0);
        sacc[nt][1] = __expf(sacc[nt][1] - mx0);
        sacc[nt][2] = __expf(sacc[nt][2] - mx1);
        sacc[nt][3] = __expf(sacc[nt][3] - mx1);
        sum0 += sacc[nt][0] + sacc[nt][1];
        sum1 += sacc[nt][2] + sacc[nt][3];
    }
    sum0 += __shfl_xor_sync(0xFFFFFFFFu, sum0, 1);
    sum0 += __shfl_xor_sync(0xFFFFFFFFu, sum0, 2);
    sum1 += __shfl_xor_sync(0xFFFFFFFFu, sum1, 1);
    sum1 += __shfl_xor_sync(0xFFFFFFFFu, sum1, 2);
    float inv0 = 1.f / sum0, inv1 = 1.f / sum1;
#pragma unroll
    for (int nt = 0; nt < 7; nt++) {
        sacc[nt][0] *= inv0; sacc[nt][1] *= inv0;
        sacc[nt][2] *= inv1; sacc[nt][3] *= inv1;
    }

    // ---- O = P V ----
    float o[4][4];
#pragma unroll
    for (int nt = 0; nt < 4; nt++)
#pragma unroll
        for (int r = 0; r < 4; r++) o[nt][r] = 0.f;

    int src0 = (lane & ~3) | (qid >> 1);
    int src1 = src0 + 2;
    bool odd = (qid & 1);

#pragma unroll
    for (int kt2 = 0; kt2 < 7; kt2++) {
        float p00 = __shfl_sync(0xFFFFFFFFu, sacc[kt2][0], src0);
        float p01 = __shfl_sync(0xFFFFFFFFu, sacc[kt2][1], src0);
        float p10 = __shfl_sync(0xFFFFFFFFu, sacc[kt2][0], src1);
        float p11 = __shfl_sync(0xFFFFFFFFu, sacc[kt2][1], src1);
        float p20 = __shfl_sync(0xFFFFFFFFu, sacc[kt2][2], src0);
        float p21 = __shfl_sync(0xFFFFFFFFu, sacc[kt2][3], src0);
        float p30 = __shfl_sync(0xFFFFFFFFu, sacc[kt2][2], src1);
        float p31 = __shfl_sync(0xFFFFFFFFu, sacc[kt2][3], src1);
        unsigned a[4];
        a[0] = __float_as_uint(odd ? p01 : p00);
        a[1] = __float_as_uint(odd ? p21 : p20);
        a[2] = __float_as_uint(odd ? p11 : p10);
        a[3] = __float_as_uint(odd ? p31 : p30);
#pragma unroll
        for (int nt = 0; nt < 4; nt++) {
            float2 bv = *(const float2*)&vt[(kt2 * 4 + nt) * 68 + lane * 2];
            mma_tf32(o[nt], a, (const unsigned*)&bv);
        }
    }

    // ---- write ctx ----
    int r0 = m0 + gid, r1 = r0 + 8;
    float* op = g_ctx + ((size_t)w * NTOK) * CCH + h * HDIM;
#pragma unroll
    for (int nt = 0; nt < 4; nt++) {
        int d = nt * 8 + 2 * qid;
        if (r0 < NTOK) { float2 t = make_float2(o[nt][0], o[nt][1]); *(float2*)&op[r0 * CCH + d] = t; }
        if (r1 < NTOK) { float2 t = make_float2(o[nt][2], o[nt][3]); *(float2*)&op[r1 * CCH + d] = t; }
    }
}

// ---------------- launch ----------------
extern "C" void kernel_launch(void* const* d_in, const int* in_sizes, int n_in,
                              void* d_out, int out_size)
{
    const float* inputs = (const float*)d_in[0];
    const float* amask  = (const float*)d_in[1];
    const float* n1g    = (const float*)d_in[2];
    const float* n1b    = (const float*)d_in[3];
    const float* qkvw   = (const float*)d_in[4];
    const float* qkvb   = (const float*)d_in[5];
    const float* rpt    = (const float*)d_in[6];
    const int*   rpi    = (const int*)d_in[7];
    const float* pw     = (const float*)d_in[8];
    const float* pb     = (const float*)d_in[9];
    const float* lw     = (const float*)d_in[10];
    const float* lb     = (const float*)d_in[11];
    float* out = (float*)d_out;

    bias2_kernel<<<(NHEAD * NWIN * BM_SZ + 255) / 256, 256>>>(rpt, rpi, amask);
    zero_pads_kernel<<<(BWIN * NHEAD * 272 + 255) / 256, 256>>>();
    ln_kernel<<<TOK / 8, 256>>>(inputs, n1g, n1b);
    gemm_kernel<0><<<dim3(9, TOK / 128), 256>>>(qkvw, qkvb, nullptr, nullptr);
    attn_kernel<<<dim3(BWIN, NHEAD), 128>>>();
    gemm_kernel<1><<<dim3(3, TOK / 128), 256>>>(pw, pb, nullptr, nullptr);
    gemm_kernel<2><<<dim3(3, TOK / 128), 256>>>(lw, lb, inputs, out);
}

// round 10
// speedup vs baseline: 1.1596x; 1.0048x over previous
#include <cuda_runtime.h>
#include <math.h>

// Problem constants
#define B_IMG   32
#define HW      56
#define CCH     192
#define NHEAD   6
#define HDIM    32
#define NTOK    49
#define NWIN    64
#define BWIN    2048
#define TOK     100352
#define SHIFT_  3
#define QSCALE  0.17677669529663687f

#define QT_SZ   2112
#define KT_SZ   1904
#define BM_SZ   3840
#define ATILE   24576   // 128 rows * 192 cols per swizzled A tile
#define NKG     24      // 192/8

// A-fragment layout: row rr (0..127), col c (0..191) within a 128-row tile:
//   off = ((rr>>4)*NKG + (c>>3))*128 + (rr&7)*16 + ((rr>>3)&1) + (((c>>2)&1)<<1) + (c&3)*4
// Warp fragment (m16n8k8 A) = LDG.128 at blk*128 + lane*4.
// B-fragment layout: W row n, col k:
//   off = ((n>>3)*NKG + (k>>3))*64 + (n&7)*8 + ((k>>2)&1) + (k&3)*2
// Warp fragment (B) = LDG.64 at blk*64 + lane*2.

__device__ __forceinline__ int a_off(int rr, int c) {
    return (((rr >> 4) * NKG + (c >> 3)) << 7) + (rr & 7) * 16
         + ((rr >> 3) & 1) + (((c >> 2) & 1) << 1) + (c & 3) * 4;
}

// ---------------- scratch ----------------
__device__ float g_xa [ (size_t)784 * ATILE ];   // LN out, A-swizzled
__device__ float g_ca [ (size_t)784 * ATILE ];   // ctx, A-swizzled
__device__ float g_ya [ (size_t)784 * ATILE ];   // proj out (window-reversed), A-swizzled
__device__ float g_q  [ (size_t)BWIN * NHEAD * QT_SZ ];
__device__ float g_k  [ (size_t)BWIN * NHEAD * KT_SZ ];
__device__ float g_v  [ (size_t)BWIN * NHEAD * KT_SZ ];
__device__ float g_bm [ (size_t)NHEAD * NWIN * BM_SZ ];
__device__ float g_wq [ 576 * 192 ];             // weights, B-swizzled
__device__ float g_wp [ 192 * 192 ];
__device__ float g_wl [ 192 * 192 ];

// ---------------- K0: combined bias+mask table ----------------
__global__ void bias2_kernel(const float* __restrict__ table, const int* __restrict__ idx,
                             const float* __restrict__ mask)
{
    int i = blockIdx.x * blockDim.x + threadIdx.x;
    if (i >= NHEAD * NWIN * BM_SZ) return;
    int c  = i % 60;
    int r  = (i / 60) & 63;
    int wi = (i / BM_SZ) & 63;
    int h  = i / (BM_SZ * NWIN);
    float v = -1e9f;
    if (r < NTOK && c < NTOK)
        v = table[idx[r * NTOK + c] * NHEAD + h] + mask[(wi * NTOK + r) * NTOK + c];
    g_bm[i] = v;
}

// ---------------- K0b: zero K/V pad rows ----------------
__global__ void zero_pads_kernel()
{
    int i = blockIdx.x * blockDim.x + threadIdx.x;
    if (i >= BWIN * NHEAD * 272) return;
    int tile = i / 272, j = i % 272;
    size_t off = (size_t)tile * KT_SZ + 1632 + j;
    g_k[off] = 0.f;
    g_v[off] = 0.f;
}

// ---------------- K0c: weight pre-swizzle (B-fragment layout) ---------------
__global__ void wswz_kernel(const float* __restrict__ wq, const float* __restrict__ wp,
                            const float* __restrict__ wl)
{
    int i = blockIdx.x * blockDim.x + threadIdx.x;
    int total = (576 + 192 + 192) * 192;
    if (i >= total) return;
    const float* src; float* dst; int n;
    if (i < 576 * 192)            { src = wq; dst = g_wq; n = i; }
    else if (i < (576+192) * 192) { src = wp; dst = g_wp; n = i - 576*192; }
    else                          { src = wl; dst = g_wl; n = i - (576+192)*192; }
    int row = n / 192, k = n % 192;
    int off = (((row >> 3) * NKG + (k >> 3)) << 6) + (row & 7) * 8
            + ((k >> 2) & 1) + (k & 3) * 2;
    dst[off] = src[n];
}

// ---------------- K1: LN + shift + window partition -> A-swizzled -----------
__global__ void __launch_bounds__(256) ln_kernel(const float* __restrict__ x,
                                                 const float* __restrict__ g,
                                                 const float* __restrict__ b)
{
    int wid  = (blockIdx.x * blockDim.x + threadIdx.x) >> 5;
    int lane = threadIdx.x & 31;
    if (wid >= TOK) return;

    int w  = wid / NTOK, n = wid % NTOK;
    int bb = w >> 6, wi = w & 63;
    int wh = wi >> 3, ww = wi & 7;
    int ii = n / 7,  jj = n % 7;
    int hh = (wh * 7 + ii + SHIFT_) % HW;
    int w2 = (ww * 7 + jj + SHIFT_) % HW;
    const float* src = x + ((size_t)bb * (HW * HW) + hh * HW + w2) * CCH;

    float vals[6];
    float s = 0.f, s2 = 0.f;
#pragma unroll
    for (int u = 0; u < 6; u++) {
        float v = src[lane + u * 32];
        vals[u] = v; s += v; s2 += v * v;
    }
#pragma unroll
    for (int off = 16; off; off >>= 1) {
        s  += __shfl_xor_sync(0xFFFFFFFFu, s,  off);
        s2 += __shfl_xor_sync(0xFFFFFFFFu, s2, off);
    }
    float mu  = s * (1.f / CCH);
    float var = s2 * (1.f / CCH) - mu * mu;
    float inv = rsqrtf(var + 1e-5f);

    float* dst = g_xa + (size_t)(wid >> 7) * ATILE;
    int rr = wid & 127;
#pragma unroll
    for (int u = 0; u < 6; u++) {
        int c = lane + u * 32;
        dst[a_off(rr, c)] = (vals[u] - mu) * inv * g[c] + b[c];
    }
}

__device__ __forceinline__ void mma_tf32(float* d, const unsigned* a, const unsigned* b) {
    asm volatile(
        "mma.sync.aligned.m16n8k8.row.col.f32.tf32.tf32.f32 "
        "{%0,%1,%2,%3}, {%4,%5,%6,%7}, {%8,%9}, {%0,%1,%2,%3};\n"
        : "+f"(d[0]), "+f"(d[1]), "+f"(d[2]), "+f"(d[3])
        : "r"(a[0]), "r"(a[1]), "r"(a[2]), "r"(a[3]), "r"(b[0]), "r"(b[1]));
}

// ---------------- GEMM: no smem, no barriers — LDG fragments + MMA ----------
// Weight array selected in DEVICE code (host-side __device__ symbol args are
// host shadows — on GB300 ATS they silently read zeros; never pass them).
template<int EPI>
__global__ void __launch_bounds__(256) gemm_kernel(const float* __restrict__ bias,
                                                   const float* __restrict__ resid,
                                                   float* __restrict__ out)
{
    const float* A   = (EPI == 0) ? g_xa : (EPI == 1 ? g_ca : g_ya);
    const float* Wsw = (EPI == 0) ? g_wq : (EPI == 1 ? g_wp : g_wl);

    int tid  = threadIdx.x;
    int lane = tid & 31, wid = tid >> 5;
    int wm = wid >> 1, wn = wid & 1;
    int gid = lane >> 2, qid = lane & 3;
    int row0 = blockIdx.y * 128;
    int col0 = blockIdx.x * 64;

    const float* Ab = A + (size_t)blockIdx.y * ATILE + ((wm * 2) * NKG) * 128 + lane * 4;
    const float* Bb = Wsw + (size_t)(blockIdx.x * 8 + wn * 4) * (NKG * 64) + lane * 2;

    float acc[2][4][4];
#pragma unroll
    for (int i = 0; i < 2; i++)
#pragma unroll
        for (int j = 0; j < 4; j++)
#pragma unroll
            for (int r = 0; r < 4; r++) acc[i][j][r] = 0.f;

#pragma unroll 6
    for (int kg = 0; kg < NKG; kg++) {
        float4 af0 = *(const float4*)(Ab + kg * 128);
        float4 af1 = *(const float4*)(Ab + NKG * 128 + kg * 128);
        float2 bf[4];
#pragma unroll
        for (int ni = 0; ni < 4; ni++)
            bf[ni] = *(const float2*)(Bb + ni * (NKG * 64) + kg * 64);
#pragma unroll
        for (int ni = 0; ni < 4; ni++) {
            mma_tf32(acc[0][ni], (const unsigned*)&af0, (const unsigned*)&bf[ni]);
            mma_tf32(acc[1][ni], (const unsigned*)&af1, (const unsigned*)&bf[ni]);
        }
    }

#pragma unroll
    for (int mi = 0; mi < 2; mi++) {
#pragma unroll
        for (int reg = 0; reg < 4; reg++) {
            int r = row0 + wm * 32 + mi * 16 + gid + ((reg >= 2) ? 8 : 0);
            int w = r / NTOK, n = r % NTOK;
            if (EPI == 0) {
#pragma unroll
                for (int ni = 0; ni < 4; ni++) {
                    int o = col0 + wn * 32 + ni * 8 + qid * 2 + (reg & 1);
                    float val = acc[mi][ni][reg] + bias[o];
                    int m = o / CCH, rem = o % CCH;
                    int h = rem >> 5, d = rem & 31;
                    size_t tb = (size_t)(w * NHEAD + h);
                    if (m == 0) {
                        int off = ((n >> 4) * 4 + (d >> 3)) * 132 + (n & 7) * 16
                                + ((n >> 3) & 1) + (((d >> 2) & 1) << 1) + (d & 3) * 4;
                        g_q[tb * QT_SZ + off] = val * QSCALE;
                    } else if (m == 1) {
                        int off = ((n >> 3) * 4 + (d >> 3)) * 68 + (n & 7) * 8
                                + ((d >> 2) & 1) + (d & 3) * 2;
                        g_k[tb * KT_SZ + off] = val;
                    } else {
                        int off = ((n >> 3) * 4 + (d >> 3)) * 68 + (d & 7) * 8
                                + (n & 3) * 2 + ((n >> 2) & 1);
                        g_v[tb * KT_SZ + off] = val;
                    }
                }
            } else if (EPI == 1) {
                int bb = w >> 6, wi = w & 63;
                int wh = wi >> 3, ww = wi & 7;
                int ii = n / 7, jj = n % 7;
                int hh = (wh * 7 + ii + SHIFT_) % HW;
                int w2 = (ww * 7 + jj + SHIFT_) % HW;
                int t  = bb * (HW * HW) + hh * HW + w2;
                float* dst = g_ya + (size_t)(t >> 7) * ATILE;
                int rr = t & 127;
#pragma unroll
                for (int ni = 0; ni < 4; ni++) {
                    int c = col0 + wn * 32 + ni * 8 + qid * 2 + (reg & 1);
                    dst[a_off(rr, c)] = acc[mi][ni][reg] + bias[c];
                }
            } else {
                const float* rs = resid + (size_t)r * CCH;
                float* dp = out + (size_t)r * CCH;
#pragma unroll
                for (int ni = 0; ni < 4; ni++) {
                    int c = col0 + wn * 32 + ni * 8 + qid * 2 + (reg & 1);
                    float v = acc[mi][ni][reg] + bias[c];
                    float ge = 0.5f * v * (1.f + erff(v * 0.70710678118654752f));
                    dp[c] = rs[c] + ge;
                }
            }
        }
    }
}

// ---------------- K3: windowed attention — ctx written A-swizzled -----------
__global__ void __launch_bounds__(128) attn_kernel()
{
    int w = blockIdx.x, h = blockIdx.y;
    int tid = threadIdx.x;
    int lane = tid & 31, wrp = tid >> 5;
    int gid = lane >> 2, qid = lane & 3;

    size_t tb = (size_t)(w * NHEAD + h);
    const float* __restrict__ qt = g_q + tb * QT_SZ;
    const float* __restrict__ kt = g_k + tb * KT_SZ;
    const float* __restrict__ vt = g_v + tb * KT_SZ;
    const float* __restrict__ bmp = g_bm + ((size_t)h * NWIN + (w & 63)) * BM_SZ;

    int m0 = wrp * 16;

    float sacc[7][4];
#pragma unroll
    for (int nt = 0; nt < 7; nt++)
#pragma unroll
        for (int r = 0; r < 4; r++) sacc[nt][r] = 0.f;

#pragma unroll
    for (int k8 = 0; k8 < 4; k8++) {
        float4 av = *(const float4*)&qt[(wrp * 4 + k8) * 132 + lane * 4];
#pragma unroll
        for (int nt = 0; nt < 7; nt++) {
            float2 bv = *(const float2*)&kt[(nt * 4 + k8) * 68 + lane * 2];
            mma_tf32(sacc[nt], (const unsigned*)&av, (const unsigned*)&bv);
        }
    }

#pragma unroll
    for (int nt = 0; nt < 7; nt++) {
        float2 t0 = *(const float2*)&bmp[(m0 + gid) * 60 + nt * 8 + 2 * qid];
        float2 t1 = *(const float2*)&bmp[(m0 + gid + 8) * 60 + nt * 8 + 2 * qid];
        sacc[nt][0] += t0.x; sacc[nt][1] += t0.y;
        sacc[nt][2] += t1.x; sacc[nt][3] += t1.y;
    }

    float mx0 = -1e30f, mx1 = -1e30f;
#pragma unroll
    for (int nt = 0; nt < 7; nt++) {
        mx0 = fmaxf(mx0, fmaxf(sacc[nt][0], sacc[nt][1]));
        mx1 = fmaxf(mx1, fmaxf(sacc[nt][2], sacc[nt][3]));
    }
    mx0 = fmaxf(mx0, __shfl_xor_sync(0xFFFFFFFFu, mx0, 1));
    mx0 = fmaxf(mx0, __shfl_xor_sync(0xFFFFFFFFu, mx0, 2));
    mx1 = fmaxf(mx1, __shfl_xor_sync(0xFFFFFFFFu, mx1, 1));
    mx1 = fmaxf(mx1, __shfl_xor_sync(0xFFFFFFFFu, mx1, 2));

    float sum0 = 0.f, sum1 = 0.f;
#pragma unroll
    for (int nt = 0; nt < 7; nt++) {
        sacc[nt][0] = __expf(sacc[nt][0] - mx0);
        sacc[nt][1] = __expf(sacc[nt][1] - mx0);
        sacc[nt][2] = __expf(sacc[nt][2] - mx1);
        sacc[nt][3] = __expf(sacc[nt][3] - mx1);
        sum0 += sacc[nt][0] + sacc[nt][1];
        sum1 += sacc[nt][2] + sacc[nt][3];
    }
    sum0 += __shfl_xor_sync(0xFFFFFFFFu, sum0, 1);
    sum0 += __shfl_xor_sync(0xFFFFFFFFu, sum0, 2);
    sum1 += __shfl_xor_sync(0xFFFFFFFFu, sum1, 1);
    sum1 += __shfl_xor_sync(0xFFFFFFFFu, sum1, 2);
    float inv0 = 1.f / sum0, inv1 = 1.f / sum1;
#pragma unroll
    for (int nt = 0; nt < 7; nt++) {
        sacc[nt][0] *= inv0; sacc[nt][1] *= inv0;
        sacc[nt][2] *= inv1; sacc[nt][3] *= inv1;
    }

    float o[4][4];
#pragma unroll
    for (int nt = 0; nt < 4; nt++)
#pragma unroll
        for (int r = 0; r < 4; r++) o[nt][r] = 0.f;

    int src0 = (lane & ~3) | (qid >> 1);
    int src1 = src0 + 2;
    bool odd = (qid & 1);

#pragma unroll
    for (int kt2 = 0; kt2 < 7; kt2++) {
        float p00 = __shfl_sync(0xFFFFFFFFu, sacc[kt2][0], src0);
        float p01 = __shfl_sync(0xFFFFFFFFu, sacc[kt2][1], src0);
        float p10 = __shfl_sync(0xFFFFFFFFu, sacc[kt2][0], src1);
        float p11 = __shfl_sync(0xFFFFFFFFu, sacc[kt2][1], src1);
        float p20 = __shfl_sync(0xFFFFFFFFu, sacc[kt2][2], src0);
        float p21 = __shfl_sync(0xFFFFFFFFu, sacc[kt2][3], src0);
        float p30 = __shfl_sync(0xFFFFFFFFu, sacc[kt2][2], src1);
        float p31 = __shfl_sync(0xFFFFFFFFu, sacc[kt2][3], src1);
        unsigned a[4];
        a[0] = __float_as_uint(odd ? p01 : p00);
        a[1] = __float_as_uint(odd ? p21 : p20);
        a[2] = __float_as_uint(odd ? p11 : p10);
        a[3] = __float_as_uint(odd ? p31 : p30);
#pragma unroll
        for (int nt = 0; nt < 4; nt++) {
            float2 bv = *(const float2*)&vt[(kt2 * 4 + nt) * 68 + lane * 2];
            mma_tf32(o[nt], a, (const unsigned*)&bv);
        }
    }

    // ---- write ctx A-swizzled ----
    int r0 = m0 + gid, r1 = r0 + 8;
    int R0 = w * NTOK + r0, R1 = w * NTOK + r1;
    float* d0 = g_ca + (size_t)(R0 >> 7) * ATILE;
    float* d1 = g_ca + (size_t)(R1 >> 7) * ATILE;
    int rr0 = R0 & 127, rr1 = R1 & 127;
#pragma unroll
    for (int nt = 0; nt < 4; nt++) {
        int c = h * HDIM + nt * 8 + 2 * qid;
        if (r0 < NTOK) {
            int of = a_off(rr0, c);
            d0[of] = o[nt][0]; d0[of + 4] = o[nt][1];
        }
        if (r1 < NTOK) {
            int of = a_off(rr1, c);
            d1[of] = o[nt][2]; d1[of + 4] = o[nt][3];
        }
    }
}

// ---------------- launch ----------------
extern "C" void kernel_launch(void* const* d_in, const int* in_sizes, int n_in,
                              void* d_out, int out_size)
{
    const float* inputs = (const float*)d_in[0];
    const float* amask  = (const float*)d_in[1];
    const float* n1g    = (const float*)d_in[2];
    const float* n1b    = (const float*)d_in[3];
    const float* qkvw   = (const float*)d_in[4];
    const float* qkvb   = (const float*)d_in[5];
    const float* rpt    = (const float*)d_in[6];
    const int*   rpi    = (const int*)d_in[7];
    const float* pw     = (const float*)d_in[8];
    const float* pb     = (const float*)d_in[9];
    const float* lw     = (const float*)d_in[10];
    const float* lb     = (const float*)d_in[11];
    float* out = (float*)d_out;

    bias2_kernel<<<(NHEAD * NWIN * BM_SZ + 255) / 256, 256>>>(rpt, rpi, amask);
    zero_pads_kernel<<<(BWIN * NHEAD * 272 + 255) / 256, 256>>>();
    wswz_kernel<<<((576 + 192 + 192) * 192 + 255) / 256, 256>>>(qkvw, pw, lw);
    ln_kernel<<<TOK / 8, 256>>>(inputs, n1g, n1b);
    gemm_kernel<0><<<dim3(9, TOK / 128), 256>>>(qkvb, nullptr, nullptr);
    attn_kernel<<<dim3(BWIN, NHEAD), 128>>>();
    gemm_kernel<1><<<dim3(3, TOK / 128), 256>>>(pb, nullptr, nullptr);
    gemm_kernel<2><<<dim3(3, TOK / 128), 256>>>(lb, inputs, out);
}

// round 11
// speedup vs baseline: 1.5409x; 1.3288x over previous
#include <cuda_runtime.h>
#include <cuda_bf16.h>
#include <math.h>

// Problem constants
#define B_IMG   32
#define HW      56
#define CCH     192
#define NHEAD   6
#define HDIM    32
#define NTOK    49
#define NWIN    64
#define BWIN    2048
#define TOK     100352
#define SHIFT_  3
#define QSCALE  0.17677669529663687f

#define QT_SZ   2112
#define KT_SZ   1904
#define BM_SZ   3840
#define NKB     12        // 192/16 k-blocks
#define AT16    12288     // words per bf16 A tile: 8 mgrp * 12 kblk * 128 words

// bf16 A-fragment layout (m16n8k16 row operand), word units (bf16x2):
//   block(16m x 16k) = 128 words; word = block*128 + ((m&7)*4 + (kp&3))*4
//                      + ((m>>3)&1) + (((kp>>2)&1)<<1)      [kp = k>>1]
//   fragment = LDG.128 at block*512B + lane*16B
// bf16 B-fragment layout (col operand): block(8n x 16k) = 64 words;
//   word = block*64 + ((n&7)*4 + (kp&3))*2 + ((kp>>2)&1)
//   fragment = LDG.64 at block*256B + lane*8B

__device__ __forceinline__ int aw_idx(int rr, int p) {   // p = c>>1
    return (((rr >> 4) * NKB + (p >> 3)) << 7)
         + (((rr & 7) * 4 + (p & 3)) << 2)
         + ((rr >> 3) & 1) + (((p >> 2) & 1) << 1);
}

__device__ __forceinline__ unsigned pk(float lo, float hi) {
    unsigned r;
    asm("cvt.rn.bf16x2.f32 %0, %1, %2;" : "=r"(r) : "f"(hi), "f"(lo));
    return r;
}

// ---------------- scratch ----------------
__device__ unsigned g_xa [ (size_t)784 * AT16 ];   // LN out, bf16 A-frag
__device__ unsigned g_ca [ (size_t)784 * AT16 ];   // ctx, bf16 A-frag
__device__ unsigned g_ya [ (size_t)784 * AT16 ];   // proj out, bf16 A-frag
__device__ float    g_q  [ (size_t)BWIN * NHEAD * QT_SZ ];   // f32 (attn tf32)
__device__ float    g_k  [ (size_t)BWIN * NHEAD * KT_SZ ];
__device__ float    g_v  [ (size_t)BWIN * NHEAD * KT_SZ ];
__device__ float    g_bm [ (size_t)NHEAD * NWIN * BM_SZ ];
__device__ unsigned g_wq [ 72 * NKB * 64 ];        // 55296 words, bf16 B-frag
__device__ unsigned g_wp [ 24 * NKB * 64 ];
__device__ unsigned g_wl [ 24 * NKB * 64 ];

// ---------------- K0: combined bias+mask table ----------------
__global__ void bias2_kernel(const float* __restrict__ table, const int* __restrict__ idx,
                             const float* __restrict__ mask)
{
    int i = blockIdx.x * blockDim.x + threadIdx.x;
    if (i >= NHEAD * NWIN * BM_SZ) return;
    int c  = i % 60;
    int r  = (i / 60) & 63;
    int wi = (i / BM_SZ) & 63;
    int h  = i / (BM_SZ * NWIN);
    float v = -1e9f;
    if (r < NTOK && c < NTOK)
        v = table[idx[r * NTOK + c] * NHEAD + h] + mask[(wi * NTOK + r) * NTOK + c];
    g_bm[i] = v;
}

// ---------------- K0b: zero K/V pad rows ----------------
__global__ void zero_pads_kernel()
{
    int i = blockIdx.x * blockDim.x + threadIdx.x;
    if (i >= BWIN * NHEAD * 272) return;
    int tile = i / 272, j = i % 272;
    size_t off = (size_t)tile * KT_SZ + 1632 + j;
    g_k[off] = 0.f;
    g_v[off] = 0.f;
}

// ---------------- K0c: weight pre-swizzle -> bf16 B-fragment ----------------
__global__ void wswz_kernel(const float* __restrict__ wq, const float* __restrict__ wp,
                            const float* __restrict__ wl)
{
    int i = blockIdx.x * blockDim.x + threadIdx.x;
    int total = (576 + 192 + 192) * 96;   // words
    if (i >= total) return;
    const float* src; unsigned* dst; int n;
    if (i < 576 * 96)           { src = wq; dst = g_wq; n = i; }
    else if (i < 768 * 96)      { src = wp; dst = g_wp; n = i - 576 * 96; }
    else                        { src = wl; dst = g_wl; n = i - 768 * 96; }
    int row = n / 96, p = n % 96;
    int w = (((row >> 3) * NKB + (p >> 3)) << 6)
          + (((row & 7) * 4 + (p & 3)) << 1) + ((p >> 2) & 1);
    dst[w] = pk(src[row * 192 + 2 * p], src[row * 192 + 2 * p + 1]);
}

// ---------------- K1: LN + shift + window partition -> bf16 A-frag ----------
__global__ void __launch_bounds__(256) ln_kernel(const float* __restrict__ x,
                                                 const float* __restrict__ g,
                                                 const float* __restrict__ b)
{
    int wid  = (blockIdx.x * blockDim.x + threadIdx.x) >> 5;
    int lane = threadIdx.x & 31;
    if (wid >= TOK) return;

    int w  = wid / NTOK, n = wid % NTOK;
    int bb = w >> 6, wi = w & 63;
    int wh = wi >> 3, ww = wi & 7;
    int ii = n / 7,  jj = n % 7;
    int hh = (wh * 7 + ii + SHIFT_) % HW;
    int w2 = (ww * 7 + jj + SHIFT_) % HW;
    const float2* src = (const float2*)(x + ((size_t)bb * (HW * HW) + hh * HW + w2) * CCH);

    float2 v[3];
    float s = 0.f, s2 = 0.f;
#pragma unroll
    for (int u = 0; u < 3; u++) {
        v[u] = src[lane + u * 32];
        s  += v[u].x + v[u].y;
        s2 += v[u].x * v[u].x + v[u].y * v[u].y;
    }
#pragma unroll
    for (int off = 16; off; off >>= 1) {
        s  += __shfl_xor_sync(0xFFFFFFFFu, s,  off);
        s2 += __shfl_xor_sync(0xFFFFFFFFu, s2, off);
    }
    float mu  = s * (1.f / CCH);
    float var = s2 * (1.f / CCH) - mu * mu;
    float inv = rsqrtf(var + 1e-5f);

    unsigned* dst = g_xa + (size_t)(wid >> 7) * AT16;
    int rr = wid & 127;
    const float2* g2 = (const float2*)g;
    const float2* b2 = (const float2*)b;
#pragma unroll
    for (int u = 0; u < 3; u++) {
        int p = lane + u * 32;
        float2 gg = g2[p], bb2 = b2[p];
        float lo = (v[u].x - mu) * inv * gg.x + bb2.x;
        float hi = (v[u].y - mu) * inv * gg.y + bb2.y;
        dst[aw_idx(rr, p)] = pk(lo, hi);
    }
}

__device__ __forceinline__ void mma_tf32(float* d, const unsigned* a, const unsigned* b) {
    asm volatile(
        "mma.sync.aligned.m16n8k8.row.col.f32.tf32.tf32.f32 "
        "{%0,%1,%2,%3}, {%4,%5,%6,%7}, {%8,%9}, {%0,%1,%2,%3};\n"
        : "+f"(d[0]), "+f"(d[1]), "+f"(d[2]), "+f"(d[3])
        : "r"(a[0]), "r"(a[1]), "r"(a[2]), "r"(a[3]), "r"(b[0]), "r"(b[1]));
}

__device__ __forceinline__ void mma_bf16(float* d, const unsigned* a, const unsigned* b) {
    asm volatile(
        "mma.sync.aligned.m16n8k16.row.col.f32.bf16.bf16.f32 "
        "{%0,%1,%2,%3}, {%4,%5,%6,%7}, {%8,%9}, {%0,%1,%2,%3};\n"
        : "+f"(d[0]), "+f"(d[1]), "+f"(d[2]), "+f"(d[3])
        : "r"(a[0]), "r"(a[1]), "r"(a[2]), "r"(a[3]), "r"(b[0]), "r"(b[1]));
}

// ---------------- GEMM: bf16 m16n8k16, no smem, LDG fragments ---------------
template<int EPI>
__global__ void __launch_bounds__(256) gemm_kernel(const float* __restrict__ bias,
                                                   const float* __restrict__ resid,
                                                   float* __restrict__ out)
{
    const unsigned* A   = (EPI == 0) ? g_xa : (EPI == 1 ? g_ca : g_ya);
    const unsigned* Wsw = (EPI == 0) ? g_wq : (EPI == 1 ? g_wp : g_wl);

    int tid  = threadIdx.x;
    int lane = tid & 31, wid = tid >> 5;
    int wm = wid >> 1, wn = wid & 1;
    int gid = lane >> 2, qid = lane & 3;
    int row0 = blockIdx.y * 128;
    int col0 = blockIdx.x * 64;

    const unsigned* Ab = A + (size_t)blockIdx.y * AT16 + (wm * 2 * NKB) * 128 + lane * 4;
    const unsigned* Bb = Wsw + (size_t)(blockIdx.x * 8 + wn * 4) * (NKB * 64) + lane * 2;

    float acc[2][4][4];
#pragma unroll
    for (int i = 0; i < 2; i++)
#pragma unroll
        for (int j = 0; j < 4; j++)
#pragma unroll
            for (int r = 0; r < 4; r++) acc[i][j][r] = 0.f;

#pragma unroll
    for (int kg = 0; kg < NKB; kg++) {
        uint4 af0 = *(const uint4*)(Ab + kg * 128);
        uint4 af1 = *(const uint4*)(Ab + NKB * 128 + kg * 128);
        uint2 bf[4];
#pragma unroll
        for (int ni = 0; ni < 4; ni++)
            bf[ni] = *(const uint2*)(Bb + ni * (NKB * 64) + kg * 64);
#pragma unroll
        for (int ni = 0; ni < 4; ni++) {
            mma_bf16(acc[0][ni], (const unsigned*)&af0, (const unsigned*)&bf[ni]);
            mma_bf16(acc[1][ni], (const unsigned*)&af1, (const unsigned*)&bf[ni]);
        }
    }

    if (EPI == 1) {
        // pack pairs (regs 0,1 -> row gid; regs 2,3 -> row gid+8) into bf16x2
#pragma unroll
        for (int mi = 0; mi < 2; mi++) {
#pragma unroll
            for (int half = 0; half < 2; half++) {
                int r = row0 + wm * 32 + mi * 16 + gid + half * 8;
                int w = r / NTOK, n = r % NTOK;
                int bb = w >> 6, wi = w & 63;
                int wh = wi >> 3, ww = wi & 7;
                int ii = n / 7, jj = n % 7;
                int hh = (wh * 7 + ii + SHIFT_) % HW;
                int w2 = (ww * 7 + jj + SHIFT_) % HW;
                int t  = bb * (HW * HW) + hh * HW + w2;
                unsigned* dst = g_ya + (size_t)(t >> 7) * AT16;
                int rr = t & 127;
#pragma unroll
                for (int ni = 0; ni < 4; ni++) {
                    int c0 = col0 + wn * 32 + ni * 8 + qid * 2;
                    float lo = acc[mi][ni][half * 2 + 0] + bias[c0];
                    float hi = acc[mi][ni][half * 2 + 1] + bias[c0 + 1];
                    dst[aw_idx(rr, c0 >> 1)] = pk(lo, hi);
                }
            }
        }
    } else {
#pragma unroll
        for (int mi = 0; mi < 2; mi++) {
#pragma unroll
            for (int reg = 0; reg < 4; reg++) {
                int r = row0 + wm * 32 + mi * 16 + gid + ((reg >= 2) ? 8 : 0);
                int w = r / NTOK, n = r % NTOK;
                if (EPI == 0) {
#pragma unroll
                    for (int ni = 0; ni < 4; ni++) {
                        int o = col0 + wn * 32 + ni * 8 + qid * 2 + (reg & 1);
                        float val = acc[mi][ni][reg] + bias[o];
                        int m = o / CCH, rem = o % CCH;
                        int h = rem >> 5, d = rem & 31;
                        size_t tb = (size_t)(w * NHEAD + h);
                        if (m == 0) {
                            int off = ((n >> 4) * 4 + (d >> 3)) * 132 + (n & 7) * 16
                                    + ((n >> 3) & 1) + (((d >> 2) & 1) << 1) + (d & 3) * 4;
                            g_q[tb * QT_SZ + off] = val * QSCALE;
                        } else if (m == 1) {
                            int off = ((n >> 3) * 4 + (d >> 3)) * 68 + (n & 7) * 8
                                    + ((d >> 2) & 1) + (d & 3) * 2;
                            g_k[tb * KT_SZ + off] = val;
                        } else {
                            int off = ((n >> 3) * 4 + (d >> 3)) * 68 + (d & 7) * 8
                                    + (n & 3) * 2 + ((n >> 2) & 1);
                            g_v[tb * KT_SZ + off] = val;
                        }
                    }
                } else {
                    const float* rs = resid + (size_t)r * CCH;
                    float* dp = out + (size_t)r * CCH;
#pragma unroll
                    for (int ni = 0; ni < 4; ni++) {
                        int c = col0 + wn * 32 + ni * 8 + qid * 2 + (reg & 1);
                        float v = acc[mi][ni][reg] + bias[c];
                        float ge = 0.5f * v * (1.f + erff(v * 0.70710678118654752f));
                        dp[c] = rs[c] + ge;
                    }
                }
            }
        }
    }
}

// ---------------- K3: windowed attention (tf32) — ctx written bf16 A-frag ---
__global__ void __launch_bounds__(128) attn_kernel()
{
    int w = blockIdx.x, h = blockIdx.y;
    int tid = threadIdx.x;
    int lane = tid & 31, wrp = tid >> 5;
    int gid = lane >> 2, qid = lane & 3;

    size_t tb = (size_t)(w * NHEAD + h);
    const float* __restrict__ qt = g_q + tb * QT_SZ;
    const float* __restrict__ kt = g_k + tb * KT_SZ;
    const float* __restrict__ vt = g_v + tb * KT_SZ;
    const float* __restrict__ bmp = g_bm + ((size_t)h * NWIN + (w & 63)) * BM_SZ;

    int m0 = wrp * 16;

    float sacc[7][4];
#pragma unroll
    for (int nt = 0; nt < 7; nt++)
#pragma unroll
        for (int r = 0; r < 4; r++) sacc[nt][r] = 0.f;

#pragma unroll
    for (int k8 = 0; k8 < 4; k8++) {
        float4 av = *(const float4*)&qt[(wrp * 4 + k8) * 132 + lane * 4];
#pragma unroll
        for (int nt = 0; nt < 7; nt++) {
            float2 bv = *(const float2*)&kt[(nt * 4 + k8) * 68 + lane * 2];
            mma_tf32(sacc[nt], (const unsigned*)&av, (const unsigned*)&bv);
        }
    }

#pragma unroll
    for (int nt = 0; nt < 7; nt++) {
        float2 t0 = *(const float2*)&bmp[(m0 + gid) * 60 + nt * 8 + 2 * qid];
        float2 t1 = *(const float2*)&bmp[(m0 + gid + 8) * 60 + nt * 8 + 2 * qid];
        sacc[nt][0] += t0.x; sacc[nt][1] += t0.y;
        sacc[nt][2] += t1.x; sacc[nt][3] += t1.y;
    }

    float mx0 = -1e30f, mx1 = -1e30f;
#pragma unroll
    for (int nt = 0; nt < 7; nt++) {
        mx0 = fmaxf(mx0, fmaxf(sacc[nt][0], sacc[nt][1]));
        mx1 = fmaxf(mx1, fmaxf(sacc[nt][2], sacc[nt][3]));
    }
    mx0 = fmaxf(mx0, __shfl_xor_sync(0xFFFFFFFFu, mx0, 1));
    mx0 = fmaxf(mx0, __shfl_xor_sync(0xFFFFFFFFu, mx0, 2));
    mx1 = fmaxf(mx1, __shfl_xor_sync(0xFFFFFFFFu, mx1, 1));
    mx1 = fmaxf(mx1, __shfl_xor_sync(0xFFFFFFFFu, mx1, 2));

    float sum0 = 0.f, sum1 = 0.f;
#pragma unroll
    for (int nt = 0; nt < 7; nt++) {
        sacc[nt][0] = __expf(sacc[nt][0] - mx0);
        sacc[nt][1] = __expf(sacc[nt][1] - mx0);
        sacc[nt][2] = __expf(sacc[nt][2] - mx1);
        sacc[nt][3] = __expf(sacc[nt][3] - mx1);
        sum0 += sacc[nt][0] + sacc[nt][1];
        sum1 += sacc[nt][2] + sacc[nt][3];
    }
    sum0 += __shfl_xor_sync(0xFFFFFFFFu, sum0, 1);
    sum0 += __shfl_xor_sync(0xFFFFFFFFu, sum0, 2);
    sum1 += __shfl_xor_sync(0xFFFFFFFFu, sum1, 1);
    sum1 += __shfl_xor_sync(0xFFFFFFFFu, sum1, 2);
    float inv0 = 1.f / sum0, inv1 = 1.f / sum1;
#pragma unroll
    for (int nt = 0; nt < 7; nt++) {
        sacc[nt][0] *= inv0; sacc[nt][1] *= inv0;
        sacc[nt][2] *= inv1; sacc[nt][3] *= inv1;
    }

    float o[4][4];
#pragma unroll
    for (int nt = 0; nt < 4; nt++)
#pragma unroll
        for (int r = 0; r < 4; r++) o[nt][r] = 0.f;

    int src0 = (lane & ~3) | (qid >> 1);
    int src1 = src0 + 2;
    bool odd = (qid & 1);

#pragma unroll
    for (int kt2 = 0; kt2 < 7; kt2++) {
        float p00 = __shfl_sync(0xFFFFFFFFu, sacc[kt2][0], src0);
        float p01 = __shfl_sync(0xFFFFFFFFu, sacc[kt2][1], src0);
        float p10 = __shfl_sync(0xFFFFFFFFu, sacc[kt2][0], src1);
        float p11 = __shfl_sync(0xFFFFFFFFu, sacc[kt2][1], src1);
        float p20 = __shfl_sync(0xFFFFFFFFu, sacc[kt2][2], src0);
        float p21 = __shfl_sync(0xFFFFFFFFu, sacc[kt2][3], src0);
        float p30 = __shfl_sync(0xFFFFFFFFu, sacc[kt2][2], src1);
        float p31 = __shfl_sync(0xFFFFFFFFu, sacc[kt2][3], src1);
        unsigned a[4];
        a[0] = __float_as_uint(odd ? p01 : p00);
        a[1] = __float_as_uint(odd ? p21 : p20);
        a[2] = __float_as_uint(odd ? p11 : p10);
        a[3] = __float_as_uint(odd ? p31 : p30);
#pragma unroll
        for (int nt = 0; nt < 4; nt++) {
            float2 bv = *(const float2*)&vt[(kt2 * 4 + nt) * 68 + lane * 2];
            mma_tf32(o[nt], a, (const unsigned*)&bv);
        }
    }

    // ---- write ctx as bf16 A-fragment words ----
    int r0 = m0 + gid, r1 = r0 + 8;
    int R0 = w * NTOK + r0, R1 = w * NTOK + r1;
    unsigned* d0 = g_ca + (size_t)(R0 >> 7) * AT16;
    unsigned* d1 = g_ca + (size_t)(R1 >> 7) * AT16;
    int rr0 = R0 & 127, rr1 = R1 & 127;
#pragma unroll
    for (int nt = 0; nt < 4; nt++) {
        int p = (h * HDIM + nt * 8 + 2 * qid) >> 1;
        if (r0 < NTOK) d0[aw_idx(rr0, p)] = pk(o[nt][0], o[nt][1]);
        if (r1 < NTOK) d1[aw_idx(rr1, p)] = pk(o[nt][2], o[nt][3]);
    }
}

// ---------------- launch ----------------
extern "C" void kernel_launch(void* const* d_in, const int* in_sizes, int n_in,
                              void* d_out, int out_size)
{
    const float* inputs = (const float*)d_in[0];
    const float* amask  = (const float*)d_in[1];
    const float* n1g    = (const float*)d_in[2];
    const float* n1b    = (const float*)d_in[3];
    const float* qkvw   = (const float*)d_in[4];
    const float* qkvb   = (const float*)d_in[5];
    const float* rpt    = (const float*)d_in[6];
    const int*   rpi    = (const int*)d_in[7];
    const float* pw     = (const float*)d_in[8];
    const float* pb     = (const float*)d_in[9];
    const float* lw     = (const float*)d_in[10];
    const float* lb     = (const float*)d_in[11];
    float* out = (float*)d_out;

    bias2_kernel<<<(NHEAD * NWIN * BM_SZ + 255) / 256, 256>>>(rpt, rpi, amask);
    zero_pads_kernel<<<(BWIN * NHEAD * 272 + 255) / 256, 256>>>();
    wswz_kernel<<<((576 + 192 + 192) * 96 + 255) / 256, 256>>>(qkvw, pw, lw);
    ln_kernel<<<TOK / 8, 256>>>(inputs, n1g, n1b);
    gemm_kernel<0><<<dim3(9, TOK / 128), 256>>>(qkvb, nullptr, nullptr);
    attn_kernel<<<dim3(BWIN, NHEAD), 128>>>();
    gemm_kernel<1><<<dim3(3, TOK / 128), 256>>>(pb, nullptr, nullptr);
    gemm_kernel<2><<<dim3(3, TOK / 128), 256>>>(lb, inputs, out);
}

// round 12
// speedup vs baseline: 2.2555x; 1.4637x over previous
#include <cuda_runtime.h>
#include <cuda_bf16.h>
#include <math.h>

// Problem constants
#define B_IMG   32
#define HW      56
#define CCH     192
#define NHEAD   6
#define HDIM    32
#define NTOK    49
#define NWIN    64
#define BWIN    2048
#define TOK     100352
#define SHIFT_  3
#define QSCALE  0.17677669529663687f

#define BM_SZ   3840
#define NKB     12        // 192/16 k-blocks (GEMM)
#define AT16    12288     // words per bf16 A tile (128 rows x 192 cols)
#define QT16    1024      // Q tile words: 4 mgrp x 2 kblk x 128
#define KT16    896       // K tile words: 7 ngrp x 2 kblk x 64
#define VT16    1024      // V tile words: 4 dgrp x 4 kblk x 64

// bf16 A-fragment (m16n8k16 row op), word = bf16x2 along k:
//   word(rr,p) = ((rr>>4)*NKB + (p>>3))*128 + ((rr&7)*4 + (p&3))*4
//              + ((rr>>3)&1) + (((p>>2)&1)<<1)          [p = k>>1]
// bf16 B-fragment (col op): word(n,p) = blk*64 + ((n&7)*4 + (p&3))*2 + ((p>>2)&1)

__device__ __forceinline__ int aw_idx(int rr, int p) {
    return (((rr >> 4) * NKB + (p >> 3)) << 7)
         + (((rr & 7) * 4 + (p & 3)) << 2)
         + ((rr >> 3) & 1) + (((p >> 2) & 1) << 1);
}

__device__ __forceinline__ unsigned pk(float lo, float hi) {
    unsigned r;
    asm("cvt.rn.bf16x2.f32 %0, %1, %2;" : "=r"(r) : "f"(hi), "f"(lo));
    return r;
}

// ---------------- scratch ----------------
__device__ unsigned g_xa [ (size_t)784 * AT16 ];
__device__ unsigned g_ca [ (size_t)784 * AT16 ];
__device__ unsigned g_ya [ (size_t)784 * AT16 ];
__device__ unsigned g_q  [ (size_t)BWIN * NHEAD * QT16 ];   // bf16 A-frag (m=row, k=d)
__device__ unsigned g_k  [ (size_t)BWIN * NHEAD * KT16 ];   // bf16 B-frag (n=key, k=d)
__device__ unsigned g_v  [ (size_t)BWIN * NHEAD * VT16 ];   // bf16 B-frag (n=d, k=key)
__device__ float    g_bm [ (size_t)NHEAD * NWIN * BM_SZ ];
__device__ unsigned g_wq [ 72 * NKB * 64 ];
__device__ unsigned g_wp [ 24 * NKB * 64 ];
__device__ unsigned g_wl [ 24 * NKB * 64 ];

// ---------------- K0: combined bias+mask table ----------------
__global__ void bias2_kernel(const float* __restrict__ table, const int* __restrict__ idx,
                             const float* __restrict__ mask)
{
    int i = blockIdx.x * blockDim.x + threadIdx.x;
    if (i >= NHEAD * NWIN * BM_SZ) return;
    int c  = i % 60;
    int r  = (i / 60) & 63;
    int wi = (i / BM_SZ) & 63;
    int h  = i / (BM_SZ * NWIN);
    float v = -1e9f;
    if (r < NTOK && c < NTOK)
        v = table[idx[r * NTOK + c] * NHEAD + h] + mask[(wi * NTOK + r) * NTOK + c];
    g_bm[i] = v;
}

// ---------------- K0c: weight pre-swizzle -> bf16 B-fragment ----------------
__global__ void wswz_kernel(const float* __restrict__ wq, const float* __restrict__ wp,
                            const float* __restrict__ wl)
{
    int i = blockIdx.x * blockDim.x + threadIdx.x;
    int total = (576 + 192 + 192) * 96;
    if (i >= total) return;
    const float* src; unsigned* dst; int n;
    if (i < 576 * 96)      { src = wq; dst = g_wq; n = i; }
    else if (i < 768 * 96) { src = wp; dst = g_wp; n = i - 576 * 96; }
    else                   { src = wl; dst = g_wl; n = i - 768 * 96; }
    int row = n / 96, p = n % 96;
    int w = (((row >> 3) * NKB + (p >> 3)) << 6)
          + (((row & 7) * 4 + (p & 3)) << 1) + ((p >> 2) & 1);
    dst[w] = pk(src[row * 192 + 2 * p], src[row * 192 + 2 * p + 1]);
}

// ---------------- K1: LN + shift + window partition -> bf16 A-frag ----------
__global__ void __launch_bounds__(256) ln_kernel(const float* __restrict__ x,
                                                 const float* __restrict__ g,
                                                 const float* __restrict__ b)
{
    int wid  = (blockIdx.x * blockDim.x + threadIdx.x) >> 5;
    int lane = threadIdx.x & 31;
    if (wid >= TOK) return;

    int w  = wid / NTOK, n = wid % NTOK;
    int bb = w >> 6, wi = w & 63;
    int wh = wi >> 3, ww = wi & 7;
    int ii = n / 7,  jj = n % 7;
    int hh = (wh * 7 + ii + SHIFT_) % HW;
    int w2 = (ww * 7 + jj + SHIFT_) % HW;
    const float2* src = (const float2*)(x + ((size_t)bb * (HW * HW) + hh * HW + w2) * CCH);

    float2 v[3];
    float s = 0.f, s2 = 0.f;
#pragma unroll
    for (int u = 0; u < 3; u++) {
        v[u] = src[lane + u * 32];
        s  += v[u].x + v[u].y;
        s2 += v[u].x * v[u].x + v[u].y * v[u].y;
    }
#pragma unroll
    for (int off = 16; off; off >>= 1) {
        s  += __shfl_xor_sync(0xFFFFFFFFu, s,  off);
        s2 += __shfl_xor_sync(0xFFFFFFFFu, s2, off);
    }
    float mu  = s * (1.f / CCH);
    float var = s2 * (1.f / CCH) - mu * mu;
    float inv = rsqrtf(var + 1e-5f);

    unsigned* dst = g_xa + (size_t)(wid >> 7) * AT16;
    int rr = wid & 127;
    const float2* g2 = (const float2*)g;
    const float2* b2 = (const float2*)b;
#pragma unroll
    for (int u = 0; u < 3; u++) {
        int p = lane + u * 32;
        float2 gg = g2[p], bb2 = b2[p];
        float lo = (v[u].x - mu) * inv * gg.x + bb2.x;
        float hi = (v[u].y - mu) * inv * gg.y + bb2.y;
        dst[aw_idx(rr, p)] = pk(lo, hi);
    }
}

__device__ __forceinline__ void mma_bf16(float* d, const unsigned* a, const unsigned* b) {
    asm volatile(
        "mma.sync.aligned.m16n8k16.row.col.f32.bf16.bf16.f32 "
        "{%0,%1,%2,%3}, {%4,%5,%6,%7}, {%8,%9}, {%0,%1,%2,%3};\n"
        : "+f"(d[0]), "+f"(d[1]), "+f"(d[2]), "+f"(d[3])
        : "r"(a[0]), "r"(a[1]), "r"(a[2]), "r"(a[3]), "r"(b[0]), "r"(b[1]));
}

// ---------------- GEMM: bf16 m16n8k16, no smem, LDG fragments ---------------
template<int EPI>
__global__ void __launch_bounds__(256) gemm_kernel(const float* __restrict__ bias,
                                                   const float* __restrict__ resid,
                                                   float* __restrict__ out)
{
    const unsigned* A   = (EPI == 0) ? g_xa : (EPI == 1 ? g_ca : g_ya);
    const unsigned* Wsw = (EPI == 0) ? g_wq : (EPI == 1 ? g_wp : g_wl);

    int tid  = threadIdx.x;
    int lane = tid & 31, wid = tid >> 5;
    int wm = wid >> 1, wn = wid & 1;
    int gid = lane >> 2, qid = lane & 3;
    int row0 = blockIdx.y * 128;
    int col0 = blockIdx.x * 64;

    const unsigned* Ab = A + (size_t)blockIdx.y * AT16 + (wm * 2 * NKB) * 128 + lane * 4;
    const unsigned* Bb = Wsw + (size_t)(blockIdx.x * 8 + wn * 4) * (NKB * 64) + lane * 2;

    float acc[2][4][4];
#pragma unroll
    for (int i = 0; i < 2; i++)
#pragma unroll
        for (int j = 0; j < 4; j++)
#pragma unroll
            for (int r = 0; r < 4; r++) acc[i][j][r] = 0.f;

#pragma unroll
    for (int kg = 0; kg < NKB; kg++) {
        uint4 af0 = *(const uint4*)(Ab + kg * 128);
        uint4 af1 = *(const uint4*)(Ab + NKB * 128 + kg * 128);
        uint2 bf[4];
#pragma unroll
        for (int ni = 0; ni < 4; ni++)
            bf[ni] = *(const uint2*)(Bb + ni * (NKB * 64) + kg * 64);
#pragma unroll
        for (int ni = 0; ni < 4; ni++) {
            mma_bf16(acc[0][ni], (const unsigned*)&af0, (const unsigned*)&bf[ni]);
            mma_bf16(acc[1][ni], (const unsigned*)&af1, (const unsigned*)&bf[ni]);
        }
    }

    if (EPI == 0) {
        // write Q/K/V in bf16 attention-fragment layouts
#pragma unroll
        for (int mi = 0; mi < 2; mi++) {
#pragma unroll
            for (int half = 0; half < 2; half++) {
                int r = row0 + wm * 32 + mi * 16 + gid + half * 8;
                int w = r / NTOK, n = r % NTOK;
#pragma unroll
                for (int ni = 0; ni < 4; ni++) {
                    int c0 = col0 + wn * 32 + ni * 8 + qid * 2;
                    float lo = acc[mi][ni][half * 2 + 0] + bias[c0];
                    float hi = acc[mi][ni][half * 2 + 1] + bias[c0 + 1];
                    int m = c0 / CCH, rem = c0 % CCH;
                    int hd = rem >> 5, d = rem & 31;
                    size_t tb = (size_t)(w * NHEAD + hd);
                    if (m == 0) {
                        int kp = d >> 1;
                        int word = ((n >> 4) * 2 + (kp >> 3)) * 128
                                 + ((n & 7) * 4 + (kp & 3)) * 4
                                 + ((n >> 3) & 1) + (((kp >> 2) & 1) << 1);
                        g_q[tb * QT16 + word] = pk(lo * QSCALE, hi * QSCALE);
                    } else if (m == 1) {
                        int kp = d >> 1;
                        int word = ((n >> 3) * 2 + (kp >> 3)) * 64
                                 + ((n & 7) * 4 + (kp & 3)) * 2 + ((kp >> 2) & 1);
                        g_k[tb * KT16 + word] = pk(lo, hi);
                    } else {
                        // V: n = key (k-dim), d = n-dim; two bf16 half-stores
                        int kb = ((n >> 1) & 3), kh = ((n >> 3) & 1), blkk = (n >> 4);
                        int w0 = ((d >> 3) * 4 + blkk) * 64 + ((d & 7) * 4 + kb) * 2 + kh;
                        __nv_bfloat16* vv = (__nv_bfloat16*)g_v;
                        vv[(tb * VT16 + w0) * 2 + (n & 1)]     = __float2bfloat16(lo);
                        vv[(tb * VT16 + w0 + 8) * 2 + (n & 1)] = __float2bfloat16(hi);
                    }
                }
            }
        }
    } else if (EPI == 1) {
#pragma unroll
        for (int mi = 0; mi < 2; mi++) {
#pragma unroll
            for (int half = 0; half < 2; half++) {
                int r = row0 + wm * 32 + mi * 16 + gid + half * 8;
                int w = r / NTOK, n = r % NTOK;
                int bb = w >> 6, wi = w & 63;
                int wh = wi >> 3, ww = wi & 7;
                int ii = n / 7, jj = n % 7;
                int hh = (wh * 7 + ii + SHIFT_) % HW;
                int w2 = (ww * 7 + jj + SHIFT_) % HW;
                int t  = bb * (HW * HW) + hh * HW + w2;
                unsigned* dst = g_ya + (size_t)(t >> 7) * AT16;
                int rr = t & 127;
#pragma unroll
                for (int ni = 0; ni < 4; ni++) {
                    int c0 = col0 + wn * 32 + ni * 8 + qid * 2;
                    float lo = acc[mi][ni][half * 2 + 0] + bias[c0];
                    float hi = acc[mi][ni][half * 2 + 1] + bias[c0 + 1];
                    dst[aw_idx(rr, c0 >> 1)] = pk(lo, hi);
                }
            }
        }
    } else {
#pragma unroll
        for (int mi = 0; mi < 2; mi++) {
#pragma unroll
            for (int reg = 0; reg < 4; reg++) {
                int r = row0 + wm * 32 + mi * 16 + gid + ((reg >= 2) ? 8 : 0);
                const float* rs = resid + (size_t)r * CCH;
                float* dp = out + (size_t)r * CCH;
#pragma unroll
                for (int ni = 0; ni < 4; ni++) {
                    int c = col0 + wn * 32 + ni * 8 + qid * 2 + (reg & 1);
                    float v = acc[mi][ni][reg] + bias[c];
                    float ge = 0.5f * v * (1.f + erff(v * 0.70710678118654752f));
                    dp[c] = rs[c] + ge;
                }
            }
        }
    }
}

// ---------------- K3: windowed attention, all-bf16, no smem -----------------
__global__ void __launch_bounds__(128) attn_kernel()
{
    int w = blockIdx.x, h = blockIdx.y;
    int tid = threadIdx.x;
    int lane = tid & 31, wrp = tid >> 5;
    int gid = lane >> 2, qid = lane & 3;

    size_t tb = (size_t)(w * NHEAD + h);
    const unsigned* __restrict__ qt = g_q + tb * QT16;
    const unsigned* __restrict__ kt = g_k + tb * KT16;
    const unsigned* __restrict__ vt = g_v + tb * VT16;
    const float* __restrict__ bmp = g_bm + ((size_t)h * NWIN + (w & 63)) * BM_SZ;

    int m0 = wrp * 16;

    // ---- S = Q K^T (2 k-blocks over head dim) ----
    float sacc[7][4];
#pragma unroll
    for (int nt = 0; nt < 7; nt++)
#pragma unroll
        for (int r = 0; r < 4; r++) sacc[nt][r] = 0.f;

    const unsigned* Ab = qt + (wrp * 2) * 128 + lane * 4;
#pragma unroll
    for (int kb = 0; kb < 2; kb++) {
        uint4 av = *(const uint4*)(Ab + kb * 128);
#pragma unroll
        for (int nt = 0; nt < 7; nt++) {
            uint2 bv = *(const uint2*)(kt + (nt * 2 + kb) * 64 + lane * 2);
            mma_bf16(sacc[nt], (const unsigned*)&av, (const unsigned*)&bv);
        }
    }

    // ---- + bias + mask ----
#pragma unroll
    for (int nt = 0; nt < 7; nt++) {
        float2 t0 = *(const float2*)&bmp[(m0 + gid) * 60 + nt * 8 + 2 * qid];
        float2 t1 = *(const float2*)&bmp[(m0 + gid + 8) * 60 + nt * 8 + 2 * qid];
        sacc[nt][0] += t0.x; sacc[nt][1] += t0.y;
        sacc[nt][2] += t1.x; sacc[nt][3] += t1.y;
    }

    // ---- softmax in registers ----
    float mx0 = -1e30f, mx1 = -1e30f;
#pragma unroll
    for (int nt = 0; nt < 7; nt++) {
        mx0 = fmaxf(mx0, fmaxf(sacc[nt][0], sacc[nt][1]));
        mx1 = fmaxf(mx1, fmaxf(sacc[nt][2], sacc[nt][3]));
    }
    mx0 = fmaxf(mx0, __shfl_xor_sync(0xFFFFFFFFu, mx0, 1));
    mx0 = fmaxf(mx0, __shfl_xor_sync(0xFFFFFFFFu, mx0, 2));
    mx1 = fmaxf(mx1, __shfl_xor_sync(0xFFFFFFFFu, mx1, 1));
    mx1 = fmaxf(mx1, __shfl_xor_sync(0xFFFFFFFFu, mx1, 2));

    float sum0 = 0.f, sum1 = 0.f;
#pragma unroll
    for (int nt = 0; nt < 7; nt++) {
        sacc[nt][0] = __expf(sacc[nt][0] - mx0);
        sacc[nt][1] = __expf(sacc[nt][1] - mx0);
        sacc[nt][2] = __expf(sacc[nt][2] - mx1);
        sacc[nt][3] = __expf(sacc[nt][3] - mx1);
        sum0 += sacc[nt][0] + sacc[nt][1];
        sum1 += sacc[nt][2] + sacc[nt][3];
    }
    sum0 += __shfl_xor_sync(0xFFFFFFFFu, sum0, 1);
    sum0 += __shfl_xor_sync(0xFFFFFFFFu, sum0, 2);
    sum1 += __shfl_xor_sync(0xFFFFFFFFu, sum1, 1);
    sum1 += __shfl_xor_sync(0xFFFFFFFFu, sum1, 2);
    float inv0 = 1.f / sum0, inv1 = 1.f / sum1;
#pragma unroll
    for (int nt = 0; nt < 7; nt++) {
        sacc[nt][0] *= inv0; sacc[nt][1] *= inv0;
        sacc[nt][2] *= inv1; sacc[nt][3] *= inv1;
    }

    // ---- O = P V : S-accumulator layout IS the bf16 A-fragment (no shuffles)
    float o[4][4];
#pragma unroll
    for (int dt = 0; dt < 4; dt++)
#pragma unroll
        for (int r = 0; r < 4; r++) o[dt][r] = 0.f;

#pragma unroll
    for (int kb = 0; kb < 4; kb++) {
        unsigned a[4];
        int n0 = 2 * kb, n1 = 2 * kb + 1;
        a[0] = pk(sacc[n0][0], sacc[n0][1]);
        a[1] = pk(sacc[n0][2], sacc[n0][3]);
        if (n1 < 7) {
            a[2] = pk(sacc[n1][0], sacc[n1][1]);
            a[3] = pk(sacc[n1][2], sacc[n1][3]);
        } else { a[2] = 0u; a[3] = 0u; }
#pragma unroll
        for (int dt = 0; dt < 4; dt++) {
            uint2 bv = *(const uint2*)(vt + (dt * 4 + kb) * 64 + lane * 2);
            mma_bf16(o[dt], a, (const unsigned*)&bv);
        }
    }

    // ---- write ctx as bf16 A-fragment words ----
    int r0 = m0 + gid, r1 = r0 + 8;
    int R0 = w * NTOK + r0, R1 = w * NTOK + r1;
    unsigned* d0 = g_ca + (size_t)(R0 >> 7) * AT16;
    unsigned* d1 = g_ca + (size_t)(R1 >> 7) * AT16;
    int rr0 = R0 & 127, rr1 = R1 & 127;
#pragma unroll
    for (int dt = 0; dt < 4; dt++) {
        int p = (h * HDIM + dt * 8 + 2 * qid) >> 1;
        if (r0 < NTOK) d0[aw_idx(rr0, p)] = pk(o[dt][0], o[dt][1]);
        if (r1 < NTOK) d1[aw_idx(rr1, p)] = pk(o[dt][2], o[dt][3]);
    }
}

// ---------------- launch ----------------
extern "C" void kernel_launch(void* const* d_in, const int* in_sizes, int n_in,
                              void* d_out, int out_size)
{
    const float* inputs = (const float*)d_in[0];
    const float* amask  = (const float*)d_in[1];
    const float* n1g    = (const float*)d_in[2];
    const float* n1b    = (const float*)d_in[3];
    const float* qkvw   = (const float*)d_in[4];
    const float* qkvb   = (const float*)d_in[5];
    const float* rpt    = (const float*)d_in[6];
    const int*   rpi    = (const int*)d_in[7];
    const float* pw     = (const float*)d_in[8];
    const float* pb     = (const float*)d_in[9];
    const float* lw     = (const float*)d_in[10];
    const float* lb     = (const float*)d_in[11];
    float* out = (float*)d_out;

    bias2_kernel<<<(NHEAD * NWIN * BM_SZ + 255) / 256, 256>>>(rpt, rpi, amask);
    wswz_kernel<<<((576 + 192 + 192) * 96 + 255) / 256, 256>>>(qkvw, pw, lw);
    ln_kernel<<<TOK / 8, 256>>>(inputs, n1g, n1b);
    gemm_kernel<0><<<dim3(9, TOK / 128), 256>>>(qkvb, nullptr, nullptr);
    attn_kernel<<<dim3(BWIN, NHEAD), 128>>>();
    gemm_kernel<1><<<dim3(3, TOK / 128), 256>>>(pb, nullptr, nullptr);
    gemm_kernel<2><<<dim3(3, TOK / 128), 256>>>(lb, inputs, out);
}

// round 13
// speedup vs baseline: 2.2603x; 1.0021x over previous
#include <cuda_runtime.h>
#include <cuda_bf16.h>
#include <math.h>

// Problem constants
#define B_IMG   32
#define HW      56
#define CCH     192
#define NHEAD   6
#define HDIM    32
#define NTOK    49
#define NWIN    64
#define BWIN    2048
#define TOK     100352
#define SHIFT_  3
#define QSCALE  0.17677669529663687f

#define BM_SZ   3840
#define NKB     12
#define AT16    12288
#define QT16    1024
#define KT16    896
#define VT16    1024

__device__ __forceinline__ int aw_idx(int rr, int p) {
    return (((rr >> 4) * NKB + (p >> 3)) << 7)
         + (((rr & 7) * 4 + (p & 3)) << 2)
         + ((rr >> 3) & 1) + (((p >> 2) & 1) << 1);
}

__device__ __forceinline__ unsigned pk(float lo, float hi) {
    unsigned r;
    asm("cvt.rn.bf16x2.f32 %0, %1, %2;" : "=r"(r) : "f"(hi), "f"(lo));
    return r;
}

// ---------------- scratch ----------------
__device__ unsigned g_xa [ (size_t)784 * AT16 ];
__device__ unsigned g_ca [ (size_t)784 * AT16 ];
__device__ unsigned g_ya [ (size_t)784 * AT16 ];
__device__ unsigned g_q  [ (size_t)BWIN * NHEAD * QT16 ];
__device__ unsigned g_k  [ (size_t)BWIN * NHEAD * KT16 ];
__device__ unsigned g_v  [ (size_t)BWIN * NHEAD * VT16 ];
__device__ float    g_bm [ (size_t)NHEAD * NWIN * BM_SZ ];
__device__ unsigned g_wq [ 72 * NKB * 64 ];
__device__ unsigned g_wp [ 24 * NKB * 64 ];
__device__ unsigned g_wl [ 24 * NKB * 64 ];

// ---------------- K0: combined bias+mask table ----------------
__global__ void bias2_kernel(const float* __restrict__ table, const int* __restrict__ idx,
                             const float* __restrict__ mask)
{
    int i = blockIdx.x * blockDim.x + threadIdx.x;
    if (i >= NHEAD * NWIN * BM_SZ) return;
    int c  = i % 60;
    int r  = (i / 60) & 63;
    int wi = (i / BM_SZ) & 63;
    int h  = i / (BM_SZ * NWIN);
    float v = -1e9f;
    if (r < NTOK && c < NTOK)
        v = table[idx[r * NTOK + c] * NHEAD + h] + mask[(wi * NTOK + r) * NTOK + c];
    g_bm[i] = v;
}

// ---------------- K0c: weight pre-swizzle -> bf16 B-fragment ----------------
__global__ void wswz_kernel(const float* __restrict__ wq, const float* __restrict__ wp,
                            const float* __restrict__ wl)
{
    int i = blockIdx.x * blockDim.x + threadIdx.x;
    int total = (576 + 192 + 192) * 96;
    if (i >= total) return;
    const float* src; unsigned* dst; int n;
    if (i < 576 * 96)      { src = wq; dst = g_wq; n = i; }
    else if (i < 768 * 96) { src = wp; dst = g_wp; n = i - 576 * 96; }
    else                   { src = wl; dst = g_wl; n = i - 768 * 96; }
    int row = n / 96, p = n % 96;
    int w = (((row >> 3) * NKB + (p >> 3)) << 6)
          + (((row & 7) * 4 + (p & 3)) << 1) + ((p >> 2) & 1);
    dst[w] = pk(src[row * 192 + 2 * p], src[row * 192 + 2 * p + 1]);
}

// ---------------- K1: LN + shift + window partition -> bf16 A-frag ----------
__global__ void __launch_bounds__(256) ln_kernel(const float* __restrict__ x,
                                                 const float* __restrict__ g,
                                                 const float* __restrict__ b)
{
    int wid  = (blockIdx.x * blockDim.x + threadIdx.x) >> 5;
    int lane = threadIdx.x & 31;
    if (wid >= TOK) return;

    int w  = wid / NTOK, n = wid % NTOK;
    int bb = w >> 6, wi = w & 63;
    int wh = wi >> 3, ww = wi & 7;
    int ii = n / 7,  jj = n % 7;
    int hh = (wh * 7 + ii + SHIFT_) % HW;
    int w2 = (ww * 7 + jj + SHIFT_) % HW;
    const float2* src = (const float2*)(x + ((size_t)bb * (HW * HW) + hh * HW + w2) * CCH);

    float2 v[3];
    float s = 0.f, s2 = 0.f;
#pragma unroll
    for (int u = 0; u < 3; u++) {
        v[u] = src[lane + u * 32];
        s  += v[u].x + v[u].y;
        s2 += v[u].x * v[u].x + v[u].y * v[u].y;
    }
#pragma unroll
    for (int off = 16; off; off >>= 1) {
        s  += __shfl_xor_sync(0xFFFFFFFFu, s,  off);
        s2 += __shfl_xor_sync(0xFFFFFFFFu, s2, off);
    }
    float mu  = s * (1.f / CCH);
    float var = s2 * (1.f / CCH) - mu * mu;
    float inv = rsqrtf(var + 1e-5f);

    unsigned* dst = g_xa + (size_t)(wid >> 7) * AT16;
    int rr = wid & 127;
    const float2* g2 = (const float2*)g;
    const float2* b2 = (const float2*)b;
#pragma unroll
    for (int u = 0; u < 3; u++) {
        int p = lane + u * 32;
        float2 gg = g2[p], bb2 = b2[p];
        float lo = (v[u].x - mu) * inv * gg.x + bb2.x;
        float hi = (v[u].y - mu) * inv * gg.y + bb2.y;
        dst[aw_idx(rr, p)] = pk(lo, hi);
    }
}

__device__ __forceinline__ void mma_bf16(float* d, const unsigned* a, const unsigned* b) {
    asm volatile(
        "mma.sync.aligned.m16n8k16.row.col.f32.bf16.bf16.f32 "
        "{%0,%1,%2,%3}, {%4,%5,%6,%7}, {%8,%9}, {%0,%1,%2,%3};\n"
        : "+f"(d[0]), "+f"(d[1]), "+f"(d[2]), "+f"(d[3])
        : "r"(a[0]), "r"(a[1]), "r"(a[2]), "r"(a[3]), "r"(b[0]), "r"(b[1]));
}

// ---------------- GEMM: bf16, no smem, software-pipelined fragments ---------
template<int EPI>
__global__ void __launch_bounds__(256, 2) gemm_kernel(const float* __restrict__ bias,
                                                      const float* __restrict__ resid,
                                                      float* __restrict__ out)
{
    const unsigned* A   = (EPI == 0) ? g_xa : (EPI == 1 ? g_ca : g_ya);
    const unsigned* Wsw = (EPI == 0) ? g_wq : (EPI == 1 ? g_wp : g_wl);

    int tid  = threadIdx.x;
    int lane = tid & 31, wid = tid >> 5;
    int wm = wid >> 1, wn = wid & 1;
    int gid = lane >> 2, qid = lane & 3;
    int row0 = blockIdx.y * 128;
    int col0 = blockIdx.x * 64;

    const unsigned* Ab = A + (size_t)blockIdx.y * AT16 + (wm * 2 * NKB) * 128 + lane * 4;
    const unsigned* Bb = Wsw + (size_t)(blockIdx.x * 8 + wn * 4) * (NKB * 64) + lane * 2;

    float acc[2][4][4];
#pragma unroll
    for (int i = 0; i < 2; i++)
#pragma unroll
        for (int j = 0; j < 4; j++)
#pragma unroll
            for (int r = 0; r < 4; r++) acc[i][j][r] = 0.f;

    // explicit double-buffered fragment pipeline
    uint4 a0c = *(const uint4*)(Ab);
    uint4 a1c = *(const uint4*)(Ab + NKB * 128);
    uint2 bc[4];
#pragma unroll
    for (int ni = 0; ni < 4; ni++)
        bc[ni] = *(const uint2*)(Bb + ni * (NKB * 64));

#pragma unroll
    for (int kg = 0; kg < NKB; kg++) {
        uint4 a0n, a1n; uint2 bn[4];
        if (kg + 1 < NKB) {
            a0n = *(const uint4*)(Ab + (kg + 1) * 128);
            a1n = *(const uint4*)(Ab + NKB * 128 + (kg + 1) * 128);
#pragma unroll
            for (int ni = 0; ni < 4; ni++)
                bn[ni] = *(const uint2*)(Bb + ni * (NKB * 64) + (kg + 1) * 64);
        }
#pragma unroll
        for (int ni = 0; ni < 4; ni++) {
            mma_bf16(acc[0][ni], (const unsigned*)&a0c, (const unsigned*)&bc[ni]);
            mma_bf16(acc[1][ni], (const unsigned*)&a1c, (const unsigned*)&bc[ni]);
        }
        if (kg + 1 < NKB) {
            a0c = a0n; a1c = a1n;
#pragma unroll
            for (int ni = 0; ni < 4; ni++) bc[ni] = bn[ni];
        }
    }

    if (EPI == 0) {
#pragma unroll
        for (int mi = 0; mi < 2; mi++) {
#pragma unroll
            for (int half = 0; half < 2; half++) {
                int r = row0 + wm * 32 + mi * 16 + gid + half * 8;
                int w = r / NTOK, n = r % NTOK;
#pragma unroll
                for (int ni = 0; ni < 4; ni++) {
                    int c0 = col0 + wn * 32 + ni * 8 + qid * 2;
                    float lo = acc[mi][ni][half * 2 + 0] + bias[c0];
                    float hi = acc[mi][ni][half * 2 + 1] + bias[c0 + 1];
                    int m = c0 / CCH, rem = c0 % CCH;
                    int hd = rem >> 5, d = rem & 31;
                    size_t tb = (size_t)(w * NHEAD + hd);
                    if (m == 0) {
                        int kp = d >> 1;
                        int word = ((n >> 4) * 2 + (kp >> 3)) * 128
                                 + ((n & 7) * 4 + (kp & 3)) * 4
                                 + ((n >> 3) & 1) + (((kp >> 2) & 1) << 1);
                        g_q[tb * QT16 + word] = pk(lo * QSCALE, hi * QSCALE);
                    } else if (m == 1) {
                        int kp = d >> 1;
                        int word = ((n >> 3) * 2 + (kp >> 3)) * 64
                                 + ((n & 7) * 4 + (kp & 3)) * 2 + ((kp >> 2) & 1);
                        g_k[tb * KT16 + word] = pk(lo, hi);
                    } else {
                        int kb = ((n >> 1) & 3), kh = ((n >> 3) & 1), blkk = (n >> 4);
                        int w0 = ((d >> 3) * 4 + blkk) * 64 + ((d & 7) * 4 + kb) * 2 + kh;
                        __nv_bfloat16* vv = (__nv_bfloat16*)g_v;
                        vv[(tb * VT16 + w0) * 2 + (n & 1)]     = __float2bfloat16(lo);
                        vv[(tb * VT16 + w0 + 8) * 2 + (n & 1)] = __float2bfloat16(hi);
                    }
                }
            }
        }
    } else if (EPI == 1) {
#pragma unroll
        for (int mi = 0; mi < 2; mi++) {
#pragma unroll
            for (int half = 0; half < 2; half++) {
                int r = row0 + wm * 32 + mi * 16 + gid + half * 8;
                int w = r / NTOK, n = r % NTOK;
                int bb = w >> 6, wi = w & 63;
                int wh = wi >> 3, ww = wi & 7;
                int ii = n / 7, jj = n % 7;
                int hh = (wh * 7 + ii + SHIFT_) % HW;
                int w2 = (ww * 7 + jj + SHIFT_) % HW;
                int t  = bb * (HW * HW) + hh * HW + w2;
                unsigned* dst = g_ya + (size_t)(t >> 7) * AT16;
                int rr = t & 127;
#pragma unroll
                for (int ni = 0; ni < 4; ni++) {
                    int c0 = col0 + wn * 32 + ni * 8 + qid * 2;
                    float lo = acc[mi][ni][half * 2 + 0] + bias[c0];
                    float hi = acc[mi][ni][half * 2 + 1] + bias[c0 + 1];
                    dst[aw_idx(rr, c0 >> 1)] = pk(lo, hi);
                }
            }
        }
    } else {
#pragma unroll
        for (int mi = 0; mi < 2; mi++) {
#pragma unroll
            for (int reg = 0; reg < 4; reg++) {
                int r = row0 + wm * 32 + mi * 16 + gid + ((reg >= 2) ? 8 : 0);
                const float* rs = resid + (size_t)r * CCH;
                float* dp = out + (size_t)r * CCH;
#pragma unroll
                for (int ni = 0; ni < 4; ni++) {
                    int c = col0 + wn * 32 + ni * 8 + qid * 2 + (reg & 1);
                    float v = acc[mi][ni][reg] + bias[c];
                    float ge = 0.5f * v * (1.f + erff(v * 0.70710678118654752f));
                    dp[c] = rs[c] + ge;
                }
            }
        }
    }
}

// ---------------- K3: windowed attention, all-bf16, no smem -----------------
__global__ void __launch_bounds__(128) attn_kernel()
{
    int w = blockIdx.x, h = blockIdx.y;
    int tid = threadIdx.x;
    int lane = tid & 31, wrp = tid >> 5;
    int gid = lane >> 2, qid = lane & 3;

    size_t tb = (size_t)(w * NHEAD + h);
    const unsigned* __restrict__ qt = g_q + tb * QT16;
    const unsigned* __restrict__ kt = g_k + tb * KT16;
    const unsigned* __restrict__ vt = g_v + tb * VT16;
    const float* __restrict__ bmp = g_bm + ((size_t)h * NWIN + (w & 63)) * BM_SZ;

    int m0 = wrp * 16;

    float sacc[7][4];
#pragma unroll
    for (int nt = 0; nt < 7; nt++)
#pragma unroll
        for (int r = 0; r < 4; r++) sacc[nt][r] = 0.f;

    const unsigned* Ab = qt + (wrp * 2) * 128 + lane * 4;
#pragma unroll
    for (int kb = 0; kb < 2; kb++) {
        uint4 av = *(const uint4*)(Ab + kb * 128);
#pragma unroll
        for (int nt = 0; nt < 7; nt++) {
            uint2 bv = *(const uint2*)(kt + (nt * 2 + kb) * 64 + lane * 2);
            mma_bf16(sacc[nt], (const unsigned*)&av, (const unsigned*)&bv);
        }
    }

#pragma unroll
    for (int nt = 0; nt < 7; nt++) {
        float2 t0 = *(const float2*)&bmp[(m0 + gid) * 60 + nt * 8 + 2 * qid];
        float2 t1 = *(const float2*)&bmp[(m0 + gid + 8) * 60 + nt * 8 + 2 * qid];
        sacc[nt][0] += t0.x; sacc[nt][1] += t0.y;
        sacc[nt][2] += t1.x; sacc[nt][3] += t1.y;
    }

    float mx0 = -1e30f, mx1 = -1e30f;
#pragma unroll
    for (int nt = 0; nt < 7; nt++) {
        mx0 = fmaxf(mx0, fmaxf(sacc[nt][0], sacc[nt][1]));
        mx1 = fmaxf(mx1, fmaxf(sacc[nt][2], sacc[nt][3]));
    }
    mx0 = fmaxf(mx0, __shfl_xor_sync(0xFFFFFFFFu, mx0, 1));
    mx0 = fmaxf(mx0, __shfl_xor_sync(0xFFFFFFFFu, mx0, 2));
    mx1 = fmaxf(mx1, __shfl_xor_sync(0xFFFFFFFFu, mx1, 1));
    mx1 = fmaxf(mx1, __shfl_xor_sync(0xFFFFFFFFu, mx1, 2));

    float sum0 = 0.f, sum1 = 0.f;
#pragma unroll
    for (int nt = 0; nt < 7; nt++) {
        sacc[nt][0] = __expf(sacc[nt][0] - mx0);
        sacc[nt][1] = __expf(sacc[nt][1] - mx0);
        sacc[nt][2] = __expf(sacc[nt][2] - mx1);
        sacc[nt][3] = __expf(sacc[nt][3] - mx1);
        sum0 += sacc[nt][0] + sacc[nt][1];
        sum1 += sacc[nt][2] + sacc[nt][3];
    }
    sum0 += __shfl_xor_sync(0xFFFFFFFFu, sum0, 1);
    sum0 += __shfl_xor_sync(0xFFFFFFFFu, sum0, 2);
    sum1 += __shfl_xor_sync(0xFFFFFFFFu, sum1, 1);
    sum1 += __shfl_xor_sync(0xFFFFFFFFu, sum1, 2);
    float inv0 = 1.f / sum0, inv1 = 1.f / sum1;
#pragma unroll
    for (int nt = 0; nt < 7; nt++) {
        sacc[nt][0] *= inv0; sacc[nt][1] *= inv0;
        sacc[nt][2] *= inv1; sacc[nt][3] *= inv1;
    }

    float o[4][4];
#pragma unroll
    for (int dt = 0; dt < 4; dt++)
#pragma unroll
        for (int r = 0; r < 4; r++) o[dt][r] = 0.f;

#pragma unroll
    for (int kb = 0; kb < 4; kb++) {
        unsigned a[4];
        int n0 = 2 * kb, n1 = 2 * kb + 1;
        a[0] = pk(sacc[n0][0], sacc[n0][1]);
        a[1] = pk(sacc[n0][2], sacc[n0][3]);
        if (n1 < 7) {
            a[2] = pk(sacc[n1][0], sacc[n1][1]);
            a[3] = pk(sacc[n1][2], sacc[n1][3]);
        } else { a[2] = 0u; a[3] = 0u; }
#pragma unroll
        for (int dt = 0; dt < 4; dt++) {
            uint2 bv = *(const uint2*)(vt + (dt * 4 + kb) * 64 + lane * 2);
            mma_bf16(o[dt], a, (const unsigned*)&bv);
        }
    }

    int r0 = m0 + gid, r1 = r0 + 8;
    int R0 = w * NTOK + r0, R1 = w * NTOK + r1;
    unsigned* d0 = g_ca + (size_t)(R0 >> 7) * AT16;
    unsigned* d1 = g_ca + (size_t)(R1 >> 7) * AT16;
    int rr0 = R0 & 127, rr1 = R1 & 127;
#pragma unroll
    for (int dt = 0; dt < 4; dt++) {
        int p = (h * HDIM + dt * 8 + 2 * qid) >> 1;
        if (r0 < NTOK) d0[aw_idx(rr0, p)] = pk(o[dt][0], o[dt][1]);
        if (r1 < NTOK) d1[aw_idx(rr1, p)] = pk(o[dt][2], o[dt][3]);
    }
}

// ---------------- launch ----------------
extern "C" void kernel_launch(void* const* d_in, const int* in_sizes, int n_in,
                              void* d_out, int out_size)
{
    const float* inputs = (const float*)d_in[0];
    const float* amask  = (const float*)d_in[1];
    const float* n1g    = (const float*)d_in[2];
    const float* n1b    = (const float*)d_in[3];
    const float* qkvw   = (const float*)d_in[4];
    const float* qkvb   = (const float*)d_in[5];
    const float* rpt    = (const float*)d_in[6];
    const int*   rpi    = (const int*)d_in[7];
    const float* pw     = (const float*)d_in[8];
    const float* pb     = (const float*)d_in[9];
    const float* lw     = (const float*)d_in[10];
    const float* lb     = (const float*)d_in[11];
    float* out = (float*)d_out;

    bias2_kernel<<<(NHEAD * NWIN * BM_SZ + 255) / 256, 256>>>(rpt, rpi, amask);
    wswz_kernel<<<((576 + 192 + 192) * 96 + 255) / 256, 256>>>(qkvw, pw, lw);
    ln_kernel<<<TOK / 8, 256>>>(inputs, n1g, n1b);
    gemm_kernel<0><<<dim3(9, TOK / 128), 256>>>(qkvb, nullptr, nullptr);
    attn_kernel<<<dim3(BWIN, NHEAD), 128>>>();
    gemm_kernel<1><<<dim3(3, TOK / 128), 256>>>(pb, nullptr, nullptr);
    gemm_kernel<2><<<dim3(3, TOK / 128), 256>>>(lb, inputs, out);
}